// round 1
// baseline (speedup 1.0000x reference)
#include <cuda_runtime.h>
#include <cuda_bf16.h>
#include <math.h>

// Problem constants
#define Bsz 2
#define NTOK 4096
#define DMODEL 1024
#define NHEADS 8
#define DH 128
#define RANK 4
#define KMAX 21
#define PADMAX 10   // KMAX/2

// Scratch (device globals; runtime allocation is forbidden)
__device__ float g_xproj[Bsz * NTOK * DMODEL];   // x @ W_in.T + b_in
__device__ float g_concat[Bsz * NTOK * DMODEL];  // concatenated head outputs

// ---------------------------------------------------------------------------
// SGEMM: C[M,N] = A[M,K] @ W[N,K]^T + bias[N]
// BM=128, BN=128, BK=16, 256 threads, 8x8 per-thread micro-tile.
// ---------------------------------------------------------------------------
#define BM 128
#define BN 128
#define BK 16
#define TM 8
#define TN 8

__global__ __launch_bounds__(256, 2)
void sgemm_tn_bias(const float* __restrict__ A,
                   const float* __restrict__ W,
                   const float* __restrict__ bias,
                   float* __restrict__ C,
                   int M, int N, int K)
{
    __shared__ float As[BK][BM];
    __shared__ float Ws[BK][BN];

    const int tid = threadIdx.x;
    const int block_row = blockIdx.y * BM;
    const int block_col = blockIdx.x * BN;
    const int tx = tid & 15;       // 0..15  (column group)
    const int ty = tid >> 4;       // 0..15  (row group)

    float acc[TM][TN];
#pragma unroll
    for (int i = 0; i < TM; i++)
#pragma unroll
        for (int j = 0; j < TN; j++)
            acc[i][j] = 0.0f;

    for (int k0 = 0; k0 < K; k0 += BK) {
        // Load A tile (BM x BK) and W tile (BN x BK), both K-contiguous.
        // 128*16 = 2048 floats = 512 float4; 256 threads -> 2 float4 each.
#pragma unroll
        for (int ld = 0; ld < 2; ld++) {
            int lin  = tid + ld * 256;      // float4 index, 0..511
            int row  = lin >> 2;            // 0..127
            int col4 = (lin & 3) << 2;      // 0,4,8,12

            float4 av = *(const float4*)(A + (size_t)(block_row + row) * K + k0 + col4);
            As[col4 + 0][row] = av.x;
            As[col4 + 1][row] = av.y;
            As[col4 + 2][row] = av.z;
            As[col4 + 3][row] = av.w;

            float4 wv = *(const float4*)(W + (size_t)(block_col + row) * K + k0 + col4);
            Ws[col4 + 0][row] = wv.x;
            Ws[col4 + 1][row] = wv.y;
            Ws[col4 + 2][row] = wv.z;
            Ws[col4 + 3][row] = wv.w;
        }
        __syncthreads();

#pragma unroll
        for (int kk = 0; kk < BK; kk++) {
            float a[TM], b[TN];
            // vector LDS (16B) to avoid 4-way bank conflicts
            float4 a0 = *(const float4*)&As[kk][ty * TM];
            float4 a1 = *(const float4*)&As[kk][ty * TM + 4];
            a[0]=a0.x; a[1]=a0.y; a[2]=a0.z; a[3]=a0.w;
            a[4]=a1.x; a[5]=a1.y; a[6]=a1.z; a[7]=a1.w;
            float4 b0 = *(const float4*)&Ws[kk][tx * TN];
            float4 b1 = *(const float4*)&Ws[kk][tx * TN + 4];
            b[0]=b0.x; b[1]=b0.y; b[2]=b0.z; b[3]=b0.w;
            b[4]=b1.x; b[5]=b1.y; b[6]=b1.z; b[7]=b1.w;
#pragma unroll
            for (int i = 0; i < TM; i++)
#pragma unroll
                for (int j = 0; j < TN; j++)
                    acc[i][j] = fmaf(a[i], b[j], acc[i][j]);
        }
        __syncthreads();
    }

    // Epilogue: add bias, write
#pragma unroll
    for (int i = 0; i < TM; i++) {
        int r = block_row + ty * TM + i;
        float* crow = C + (size_t)r * N + block_col + tx * TN;
#pragma unroll
        for (int j = 0; j < TN; j += 4) {
            float4 v;
            v.x = acc[i][j + 0] + bias[block_col + tx * TN + j + 0];
            v.y = acc[i][j + 1] + bias[block_col + tx * TN + j + 1];
            v.z = acc[i][j + 2] + bias[block_col + tx * TN + j + 2];
            v.w = acc[i][j + 3] + bias[block_col + tx * TN + j + 3];
            *(float4*)(crow + j) = v;
        }
    }
}

// ---------------------------------------------------------------------------
// Per-head dynamic-kernel conv.
// Block: 256 threads (8 warps), handles 32 tokens of one (b, h).
// Each warp processes 4 tokens; each lane owns 4 of the 128 channels.
// ---------------------------------------------------------------------------
#define TOK_PER_BLK 32
#define TILE_ROWS (TOK_PER_BLK + 2 * PADMAX)   // 52

__global__ __launch_bounds__(256, 4)
void dka_conv_kernel(const float* __restrict__ xproj,
                     const float* __restrict__ Wc,
                     const float* __restrict__ A,
                     const float* __restrict__ V,
                     const float* __restrict__ base,
                     const float* __restrict__ alphas,
                     float* __restrict__ concat)
{
    __shared__ float xs[TILE_ROWS][DH];          // 26624 B
    __shared__ float Wc_s[DH * RANK];            //  2048 B
    __shared__ float A_s[RANK * KMAX];           //   336 B
    __shared__ float V_s[RANK * DH];             //  2048 B
    __shared__ float base_s[KMAX * DH];          // 10752 B

    const int tid  = threadIdx.x;
    const int lane = tid & 31;
    const int warp = tid >> 5;

    const int chunk = blockIdx.x;          // 0 .. N/32-1
    const int h     = blockIdx.y;          // 0 .. 7
    const int b     = blockIdx.z;          // 0 .. 1
    const int start = chunk * TOK_PER_BLK;

    const int KH   = (h < 2) ? 3 : (h < 4) ? 7 : (h < 6) ? 11 : 21;
    const int padH = KH >> 1;

    // --- load x tile with halo (zero-padded at sequence boundaries) ---
    const float* xp_base = xproj + ((size_t)b * NTOK) * DMODEL + h * DH;
    for (int idx = tid; idx < TILE_ROWS * DH; idx += 256) {
        int row = idx >> 7;          // /128
        int col = idx & 127;
        int gn  = start - PADMAX + row;
        float v = 0.0f;
        if (gn >= 0 && gn < NTOK)
            v = xp_base[(size_t)gn * DMODEL + col];
        xs[row][col] = v;
    }
    // --- load per-head weights ---
    for (int idx = tid; idx < DH * RANK; idx += 256)
        Wc_s[idx] = Wc[(size_t)h * DH * RANK + idx];
    for (int idx = tid; idx < RANK * KMAX; idx += 256)
        A_s[idx] = A[(size_t)h * RANK * KMAX + idx];
    for (int idx = tid; idx < RANK * DH; idx += 256)
        V_s[idx] = V[(size_t)h * RANK * DH + idx];
    for (int idx = tid; idx < KMAX * DH; idx += 256)
        base_s[idx] = base[(size_t)h * KMAX * DH + idx];
    __syncthreads();

    const float alpha = 1.0f / (1.0f + __expf(-alphas[h]));
    const float oma   = 1.0f - alpha;

    // --- per-token work: each warp handles tokens lt = warp + 8*i ---
    for (int it = 0; it < TOK_PER_BLK / 8; it++) {
        const int lt     = warp + 8 * it;     // local token 0..31
        const int center = lt + PADMAX;

        // channels owned by this lane
        float xv[4];
#pragma unroll
        for (int i = 0; i < 4; i++)
            xv[i] = xs[center][lane + 32 * i];

        // c[r] = sum_d x_h[d] * Wc[d][r]  (warp reduction)
        float c0 = 0.f, c1 = 0.f, c2 = 0.f, c3 = 0.f;
#pragma unroll
        for (int i = 0; i < 4; i++) {
            int d = lane + 32 * i;
            float x = xv[i];
            c0 = fmaf(x, Wc_s[d * RANK + 0], c0);
            c1 = fmaf(x, Wc_s[d * RANK + 1], c1);
            c2 = fmaf(x, Wc_s[d * RANK + 2], c2);
            c3 = fmaf(x, Wc_s[d * RANK + 3], c3);
        }
#pragma unroll
        for (int off = 16; off > 0; off >>= 1) {
            c0 += __shfl_xor_sync(0xffffffffu, c0, off);
            c1 += __shfl_xor_sync(0xffffffffu, c1, off);
            c2 += __shfl_xor_sync(0xffffffffu, c2, off);
            c3 += __shfl_xor_sync(0xffffffffu, c3, off);
        }

        float acc[4] = {0.f, 0.f, 0.f, 0.f};
        for (int k = 0; k < KH; k++) {
            const float ca0 = c0 * A_s[0 * KMAX + k];
            const float ca1 = c1 * A_s[1 * KMAX + k];
            const float ca2 = c2 * A_s[2 * KMAX + k];
            const float ca3 = c3 * A_s[3 * KMAX + k];
            const int row = center - padH + k;
#pragma unroll
            for (int i = 0; i < 4; i++) {
                int d = lane + 32 * i;
                float dyn = ca0 * V_s[0 * DH + d]
                          + ca1 * V_s[1 * DH + d]
                          + ca2 * V_s[2 * DH + d]
                          + ca3 * V_s[3 * DH + d];
                float kh = alpha * dyn + oma * base_s[k * DH + d];
                acc[i] = fmaf(kh, xs[row][d], acc[i]);
            }
        }

        const int n = start + lt;
        float* out = concat + ((size_t)b * NTOK + n) * DMODEL + h * DH;
#pragma unroll
        for (int i = 0; i < 4; i++)
            out[lane + 32 * i] = acc[i];
    }
}

// ---------------------------------------------------------------------------
// Launch
// ---------------------------------------------------------------------------
extern "C" void kernel_launch(void* const* d_in, const int* in_sizes, int n_in,
                              void* d_out, int out_size)
{
    const float* x      = (const float*)d_in[0];  // (B, N, 1024)
    const float* W_in   = (const float*)d_in[1];  // (1024, 1024)
    const float* b_in   = (const float*)d_in[2];  // (1024,)
    const float* W_out  = (const float*)d_in[3];  // (1024, 1024)
    const float* b_out  = (const float*)d_in[4];  // (1024,)
    const float* Wc     = (const float*)d_in[5];  // (H, DH, R)
    const float* A      = (const float*)d_in[6];  // (H, R, KMAX)
    const float* V      = (const float*)d_in[7];  // (H, R, DH)
    const float* base   = (const float*)d_in[8];  // (H, KMAX, DH)
    const float* alphas = (const float*)d_in[9];  // (H,)
    float* out = (float*)d_out;

    float* xproj;  cudaGetSymbolAddress((void**)&xproj,  g_xproj);
    float* concat; cudaGetSymbolAddress((void**)&concat, g_concat);

    const int M = Bsz * NTOK;   // 8192
    const int N = DMODEL;       // 1024
    const int K = DMODEL;       // 1024

    // GEMM1: xproj = x @ W_in^T + b_in
    {
        dim3 grid(N / BN, M / BM);
        sgemm_tn_bias<<<grid, 256>>>(x, W_in, b_in, xproj, M, N, K);
    }
    // Per-head dynamic conv -> concat
    {
        dim3 grid(NTOK / TOK_PER_BLK, NHEADS, Bsz);
        dka_conv_kernel<<<grid, 256>>>(xproj, Wc, A, V, base, alphas, concat);
    }
    // GEMM2: out = concat @ W_out^T + b_out
    {
        dim3 grid(N / BN, M / BM);
        sgemm_tn_bias<<<grid, 256>>>(concat, W_out, b_out, out, M, N, K);
    }
}

// round 6
// speedup vs baseline: 2.0618x; 2.0618x over previous
#include <cuda_runtime.h>
#include <cuda_bf16.h>
#include <cstdint>
#include <math.h>

// Problem constants
#define Bsz 2
#define NTOK 4096
#define DMODEL 1024
#define NHEADS 8
#define DH 128
#define RANK 4
#define KMAX 21
#define PADMAX 10   // KMAX/2

#define GM (Bsz * NTOK)   // 8192
#define GK DMODEL         // 1024
#define GN DMODEL         // 1024

// Scratch (device globals; runtime allocation is forbidden)
__device__ float g_xproj[GM * GK];                 // x @ W_in.T + b_in (fp32 for conv)
__device__ __nv_bfloat16 g_xhi[GM * GK];           // split of x
__device__ __nv_bfloat16 g_xlo[GM * GK];
__device__ __nv_bfloat16 g_chi[GM * GK];           // split of concat (written by conv)
__device__ __nv_bfloat16 g_clo[GM * GK];
__device__ __nv_bfloat16 g_wih[GN * GK];           // split of W_in
__device__ __nv_bfloat16 g_wil[GN * GK];
__device__ __nv_bfloat16 g_woh[GN * GK];           // split of W_out
__device__ __nv_bfloat16 g_wol[GN * GK];

// ===========================================================================
// Elementwise fp32 -> (bf16 hi, bf16 lo) split.  n4 = element count / 4.
// ===========================================================================
__global__ __launch_bounds__(256)
void split_bf16(const float4* __restrict__ in, uint2* __restrict__ hi,
                uint2* __restrict__ lo, int n4)
{
    int i = blockIdx.x * 256 + threadIdx.x;
    if (i >= n4) return;
    float4 v = in[i];
    __nv_bfloat162 h01 = __floats2bfloat162_rn(v.x, v.y);
    __nv_bfloat162 h23 = __floats2bfloat162_rn(v.z, v.w);
    float2 f01 = __bfloat1622float2(h01);
    float2 f23 = __bfloat1622float2(h23);
    __nv_bfloat162 l01 = __floats2bfloat162_rn(v.x - f01.x, v.y - f01.y);
    __nv_bfloat162 l23 = __floats2bfloat162_rn(v.z - f23.x, v.w - f23.y);
    uint2 uh, ul;
    uh.x = *reinterpret_cast<const uint32_t*>(&h01);
    uh.y = *reinterpret_cast<const uint32_t*>(&h23);
    ul.x = *reinterpret_cast<const uint32_t*>(&l01);
    ul.y = *reinterpret_cast<const uint32_t*>(&l23);
    hi[i] = uh;
    lo[i] = ul;
}

// ===========================================================================
// mma.sync GEMM:  C[M,N] = A[M,K] @ W[N,K]^T + bias[N]   (fp32 out)
// A, W given pre-split as bf16 hi/lo.  D = AhBh + AhBl + AlBh (fp32 accum).
// CTA tile 128x128, 8 warps (warp tile 32x64), K-chunk 32, double-buffered
// cp.async.  Smem rows padded to 80B (conflict-free ldmatrix, 16B aligned).
// ===========================================================================
#define CH_K 32
#define NCHUNK (GK / CH_K)     // 32
#define ROWB 80                // bytes per smem row (32 bf16 + 16B pad)
#define TSZ (128 * ROWB)       // 10240 bytes per tensor tile
#define STG (4 * TSZ)          // 40960 bytes per stage (Ahi,Alo,Bhi,Blo)
#define GSMEM (2 * STG)        // 81920 bytes

__device__ __forceinline__ uint32_t smem_u32(const void* p) {
    uint32_t a;
    asm("{ .reg .u64 t; cvta.to.shared.u64 t, %1; cvt.u32.u64 %0, t; }"
        : "=r"(a) : "l"(p));
    return a;
}

#define LDMX4(r, addr) \
    asm volatile("ldmatrix.sync.aligned.m8n8.x4.shared.b16 {%0,%1,%2,%3}, [%4];" \
        : "=r"((r)[0]), "=r"((r)[1]), "=r"((r)[2]), "=r"((r)[3]) : "r"(addr))

#define MMA16816(c, a, b0, b1) \
    asm volatile("mma.sync.aligned.m16n8k16.row.col.f32.bf16.bf16.f32 " \
        "{%0,%1,%2,%3}, {%4,%5,%6,%7}, {%8,%9}, {%0,%1,%2,%3};" \
        : "+f"((c)[0]), "+f"((c)[1]), "+f"((c)[2]), "+f"((c)[3]) \
        : "r"((a)[0]), "r"((a)[1]), "r"((a)[2]), "r"((a)[3]), "r"(b0), "r"(b1))

__global__ __launch_bounds__(256, 1)
void gemm_mma(const __nv_bfloat16* __restrict__ Ahi,
              const __nv_bfloat16* __restrict__ Alo,
              const __nv_bfloat16* __restrict__ Bhi,
              const __nv_bfloat16* __restrict__ Blo,
              const float* __restrict__ bias,
              float* __restrict__ C)
{
    extern __shared__ __align__(128) char smem[];
    const uint32_t sb = smem_u32(smem);
    const int tid = threadIdx.x;
    const int lane = tid & 31;
    const int wid = tid >> 5;
    const int warp_m = wid & 3;        // 4 warps along M (32 rows each)
    const int warp_n = wid >> 2;       // 2 warps along N (64 cols each)
    const int row0 = blockIdx.y * 128;
    const int col0 = blockIdx.x * 128;

    const __nv_bfloat16* gsrc[4];
    gsrc[0] = Ahi + (size_t)row0 * GK;
    gsrc[1] = Alo + (size_t)row0 * GK;
    gsrc[2] = Bhi + (size_t)col0 * GK;
    gsrc[3] = Blo + (size_t)col0 * GK;

    float acc[2][8][4];
#pragma unroll
    for (int mt = 0; mt < 2; mt++)
#pragma unroll
        for (int nt = 0; nt < 8; nt++)
#pragma unroll
            for (int j = 0; j < 4; j++)
                acc[mt][nt][j] = 0.0f;

    // per-thread load assignment: 2048 16B-chunks per stage / 256 thr = 8
    const int ld_row = tid >> 2;           // 0..63? no: idx>>2 below
    (void)ld_row;

#define ISSUE_STAGE(CH, SG)                                                   \
    do {                                                                      \
        const int _k0 = (CH) * CH_K;                                          \
        _Pragma("unroll")                                                     \
        for (int _t = 0; _t < 4; _t++) {                                      \
            _Pragma("unroll")                                                 \
            for (int _j = 0; _j < 2; _j++) {                                  \
                int _idx = tid + _j * 256;     /* 0..511 */                   \
                int _r = _idx >> 2;            /* 0..127 */                   \
                int _c = _idx & 3;             /* 16B chunk in row */         \
                const __nv_bfloat16* _g = gsrc[_t] + (size_t)_r * GK + _k0 + _c * 8; \
                uint32_t _s = sb + (SG) * STG + _t * TSZ + _r * ROWB + _c * 16; \
                asm volatile("cp.async.cg.shared.global [%0], [%1], 16;"      \
                             :: "r"(_s), "l"(_g));                            \
            }                                                                 \
        }                                                                     \
        asm volatile("cp.async.commit_group;");                               \
    } while (0)

    ISSUE_STAGE(0, 0);

    for (int ch = 0; ch < NCHUNK; ch++) {
        const int cur = ch & 1;
        if (ch + 1 < NCHUNK) {
            ISSUE_STAGE(ch + 1, cur ^ 1);
            asm volatile("cp.async.wait_group 1;");
        } else {
            asm volatile("cp.async.wait_group 0;");
        }
        __syncthreads();

        const uint32_t stBase = sb + cur * STG;
#pragma unroll
        for (int ks = 0; ks < 2; ks++) {
            // --- A fragments: rows warp_m*32, two m16 tiles, hi & lo ---
            uint32_t a_hi[2][4], a_lo[2][4];
            {
                const uint32_t kb = (ks * 16 + (lane >> 4) * 8) * 2;
#pragma unroll
                for (int mt = 0; mt < 2; mt++) {
                    uint32_t ad = stBase
                                + (warp_m * 32 + mt * 16 + (lane & 15)) * ROWB + kb;
                    LDMX4(a_hi[mt], ad);
                    LDMX4(a_lo[mt], ad + TSZ);
                }
            }
            // --- B fragments per n16 pair; immediately consumed ---
#pragma unroll
            for (int pr = 0; pr < 4; pr++) {
                const uint32_t bd = stBase + 2 * TSZ
                    + (warp_n * 64 + pr * 16 + ((lane >> 4) & 1) * 8 + (lane & 7)) * ROWB
                    + (ks * 16 + ((lane >> 3) & 1) * 8) * 2;
                uint32_t b_hi[4], b_lo[4];
                LDMX4(b_hi, bd);
                LDMX4(b_lo, bd + TSZ);
#pragma unroll
                for (int mt = 0; mt < 2; mt++) {
                    MMA16816(acc[mt][2 * pr],     a_hi[mt], b_hi[0], b_hi[1]);
                    MMA16816(acc[mt][2 * pr],     a_hi[mt], b_lo[0], b_lo[1]);
                    MMA16816(acc[mt][2 * pr],     a_lo[mt], b_hi[0], b_hi[1]);
                    MMA16816(acc[mt][2 * pr + 1], a_hi[mt], b_hi[2], b_hi[3]);
                    MMA16816(acc[mt][2 * pr + 1], a_hi[mt], b_lo[2], b_lo[3]);
                    MMA16816(acc[mt][2 * pr + 1], a_lo[mt], b_hi[2], b_hi[3]);
                }
            }
        }
        __syncthreads();
    }
#undef ISSUE_STAGE

    // Epilogue: mma c-fragment layout -> C with bias
#pragma unroll
    for (int mt = 0; mt < 2; mt++) {
        const int r = row0 + warp_m * 32 + mt * 16 + (lane >> 2);
#pragma unroll
        for (int nt = 0; nt < 8; nt++) {
            const int cc = col0 + warp_n * 64 + nt * 8 + (lane & 3) * 2;
            const float b0 = bias[cc], b1 = bias[cc + 1];
            float2 v0, v1;
            v0.x = acc[mt][nt][0] + b0;  v0.y = acc[mt][nt][1] + b1;
            v1.x = acc[mt][nt][2] + b0;  v1.y = acc[mt][nt][3] + b1;
            *(float2*)(C + (size_t)r * GN + cc) = v0;
            *(float2*)(C + (size_t)(r + 8) * GN + cc) = v1;
        }
    }
}

// ---------------------------------------------------------------------------
// Per-head dynamic-kernel conv; epilogue now emits bf16 hi/lo split directly.
// ---------------------------------------------------------------------------
#define TOK_PER_BLK 32
#define TILE_ROWS (TOK_PER_BLK + 2 * PADMAX)   // 52

__global__ __launch_bounds__(256, 4)
void dka_conv_kernel(const float* __restrict__ xproj,
                     const float* __restrict__ Wc,
                     const float* __restrict__ A,
                     const float* __restrict__ V,
                     const float* __restrict__ base,
                     const float* __restrict__ alphas,
                     __nv_bfloat16* __restrict__ chi,
                     __nv_bfloat16* __restrict__ clo)
{
    __shared__ float xs[TILE_ROWS][DH];
    __shared__ float Wc_s[DH * RANK];
    __shared__ float A_s[RANK * KMAX];
    __shared__ float V_s[RANK * DH];
    __shared__ float base_s[KMAX * DH];

    const int tid  = threadIdx.x;
    const int lane = tid & 31;
    const int warp = tid >> 5;

    const int chunk = blockIdx.x;
    const int h     = blockIdx.y;
    const int b     = blockIdx.z;
    const int start = chunk * TOK_PER_BLK;

    const int KH   = (h < 2) ? 3 : (h < 4) ? 7 : (h < 6) ? 11 : 21;
    const int padH = KH >> 1;

    const float* xp_base = xproj + ((size_t)b * NTOK) * DMODEL + h * DH;
    for (int idx = tid; idx < TILE_ROWS * DH; idx += 256) {
        int row = idx >> 7;
        int col = idx & 127;
        int gn  = start - PADMAX + row;
        float v = 0.0f;
        if (gn >= 0 && gn < NTOK)
            v = xp_base[(size_t)gn * DMODEL + col];
        xs[row][col] = v;
    }
    for (int idx = tid; idx < DH * RANK; idx += 256)
        Wc_s[idx] = Wc[(size_t)h * DH * RANK + idx];
    for (int idx = tid; idx < RANK * KMAX; idx += 256)
        A_s[idx] = A[(size_t)h * RANK * KMAX + idx];
    for (int idx = tid; idx < RANK * DH; idx += 256)
        V_s[idx] = V[(size_t)h * RANK * DH + idx];
    for (int idx = tid; idx < KMAX * DH; idx += 256)
        base_s[idx] = base[(size_t)h * KMAX * DH + idx];
    __syncthreads();

    const float alpha = 1.0f / (1.0f + __expf(-alphas[h]));
    const float oma   = 1.0f - alpha;

    for (int it = 0; it < TOK_PER_BLK / 8; it++) {
        const int lt     = warp + 8 * it;
        const int center = lt + PADMAX;

        float xv[4];
#pragma unroll
        for (int i = 0; i < 4; i++)
            xv[i] = xs[center][lane + 32 * i];

        float c0 = 0.f, c1 = 0.f, c2 = 0.f, c3 = 0.f;
#pragma unroll
        for (int i = 0; i < 4; i++) {
            int d = lane + 32 * i;
            float x = xv[i];
            c0 = fmaf(x, Wc_s[d * RANK + 0], c0);
            c1 = fmaf(x, Wc_s[d * RANK + 1], c1);
            c2 = fmaf(x, Wc_s[d * RANK + 2], c2);
            c3 = fmaf(x, Wc_s[d * RANK + 3], c3);
        }
#pragma unroll
        for (int off = 16; off > 0; off >>= 1) {
            c0 += __shfl_xor_sync(0xffffffffu, c0, off);
            c1 += __shfl_xor_sync(0xffffffffu, c1, off);
            c2 += __shfl_xor_sync(0xffffffffu, c2, off);
            c3 += __shfl_xor_sync(0xffffffffu, c3, off);
        }

        float acc[4] = {0.f, 0.f, 0.f, 0.f};
        for (int k = 0; k < KH; k++) {
            const float ca0 = c0 * A_s[0 * KMAX + k];
            const float ca1 = c1 * A_s[1 * KMAX + k];
            const float ca2 = c2 * A_s[2 * KMAX + k];
            const float ca3 = c3 * A_s[3 * KMAX + k];
            const int row = center - padH + k;
#pragma unroll
            for (int i = 0; i < 4; i++) {
                int d = lane + 32 * i;
                float dyn = ca0 * V_s[0 * DH + d]
                          + ca1 * V_s[1 * DH + d]
                          + ca2 * V_s[2 * DH + d]
                          + ca3 * V_s[3 * DH + d];
                float kh = alpha * dyn + oma * base_s[k * DH + d];
                acc[i] = fmaf(kh, xs[row][d], acc[i]);
            }
        }

        const int n = start + lt;
        const size_t ob = ((size_t)b * NTOK + n) * DMODEL + h * DH;
#pragma unroll
        for (int i = 0; i < 4; i++) {
            float a = acc[i];
            __nv_bfloat16 hbf = __float2bfloat16(a);
            float hf = __bfloat162float(hbf);
            chi[ob + lane + 32 * i] = hbf;
            clo[ob + lane + 32 * i] = __float2bfloat16(a - hf);
        }
    }
}

// ---------------------------------------------------------------------------
// Launch
// ---------------------------------------------------------------------------
extern "C" void kernel_launch(void* const* d_in, const int* in_sizes, int n_in,
                              void* d_out, int out_size)
{
    const float* x      = (const float*)d_in[0];
    const float* W_in   = (const float*)d_in[1];
    const float* b_in   = (const float*)d_in[2];
    const float* W_out  = (const float*)d_in[3];
    const float* b_out  = (const float*)d_in[4];
    const float* Wc     = (const float*)d_in[5];
    const float* A      = (const float*)d_in[6];
    const float* V      = (const float*)d_in[7];
    const float* base   = (const float*)d_in[8];
    const float* alphas = (const float*)d_in[9];
    float* out = (float*)d_out;

    float* xproj; cudaGetSymbolAddress((void**)&xproj, g_xproj);
    __nv_bfloat16 *xhi, *xlo, *chi, *clo, *wih, *wil, *woh, *wol;
    cudaGetSymbolAddress((void**)&xhi, g_xhi);
    cudaGetSymbolAddress((void**)&xlo, g_xlo);
    cudaGetSymbolAddress((void**)&chi, g_chi);
    cudaGetSymbolAddress((void**)&clo, g_clo);
    cudaGetSymbolAddress((void**)&wih, g_wih);
    cudaGetSymbolAddress((void**)&wil, g_wil);
    cudaGetSymbolAddress((void**)&woh, g_woh);
    cudaGetSymbolAddress((void**)&wol, g_wol);

    cudaFuncSetAttribute(gemm_mma, cudaFuncAttributeMaxDynamicSharedMemorySize, GSMEM);

    // Splits
    {
        int n4x = GM * GK / 4;          // 2,097,152
        split_bf16<<<(n4x + 255) / 256, 256>>>((const float4*)x,
            (uint2*)xhi, (uint2*)xlo, n4x);
        int n4w = GN * GK / 4;          // 262,144
        split_bf16<<<(n4w + 255) / 256, 256>>>((const float4*)W_in,
            (uint2*)wih, (uint2*)wil, n4w);
        split_bf16<<<(n4w + 255) / 256, 256>>>((const float4*)W_out,
            (uint2*)woh, (uint2*)wol, n4w);
    }
    // GEMM1: xproj = x @ W_in^T + b_in
    {
        dim3 grid(GN / 128, GM / 128);   // (8, 64)
        gemm_mma<<<grid, 256, GSMEM>>>(xhi, xlo, wih, wil, b_in, xproj);
    }
    // Per-head dynamic conv -> concat (bf16 hi/lo)
    {
        dim3 grid(NTOK / TOK_PER_BLK, NHEADS, Bsz);
        dka_conv_kernel<<<grid, 256>>>(xproj, Wc, A, V, base, alphas, chi, clo);
    }
    // GEMM2: out = concat @ W_out^T + b_out
    {
        dim3 grid(GN / 128, GM / 128);
        gemm_mma<<<grid, 256, GSMEM>>>(chi, clo, woh, wol, b_out, out);
    }
}

// round 7
// speedup vs baseline: 2.3102x; 1.1205x over previous
#include <cuda_runtime.h>
#include <cuda_bf16.h>
#include <cstdint>
#include <math.h>

// Problem constants
#define Bsz 2
#define NTOK 4096
#define DMODEL 1024
#define NHEADS 8
#define DH 128
#define RANK 4
#define KMAX 21
#define PADMAX 10   // KMAX/2

#define GM (Bsz * NTOK)   // 8192
#define GK DMODEL         // 1024
#define GN DMODEL         // 1024

// Scratch (device globals; runtime allocation is forbidden)
__device__ float g_xproj[GM * GK];                 // x @ W_in.T + b_in (fp32 for conv)
__device__ __nv_bfloat16 g_xhi[GM * GK];           // split of x
__device__ __nv_bfloat16 g_xlo[GM * GK];
__device__ __nv_bfloat16 g_chi[GM * GK];           // split of concat (written by conv)
__device__ __nv_bfloat16 g_clo[GM * GK];
__device__ __nv_bfloat16 g_wih[GN * GK];           // split of W_in
__device__ __nv_bfloat16 g_wil[GN * GK];
__device__ __nv_bfloat16 g_woh[GN * GK];           // split of W_out
__device__ __nv_bfloat16 g_wol[GN * GK];

// ===========================================================================
// Elementwise fp32 -> (bf16 hi, bf16 lo) split.  n4 = element count / 4.
// ===========================================================================
__global__ __launch_bounds__(256)
void split_bf16(const float4* __restrict__ in, uint2* __restrict__ hi,
                uint2* __restrict__ lo, int n4)
{
    int i = blockIdx.x * 256 + threadIdx.x;
    if (i >= n4) return;
    float4 v = in[i];
    __nv_bfloat162 h01 = __floats2bfloat162_rn(v.x, v.y);
    __nv_bfloat162 h23 = __floats2bfloat162_rn(v.z, v.w);
    float2 f01 = __bfloat1622float2(h01);
    float2 f23 = __bfloat1622float2(h23);
    __nv_bfloat162 l01 = __floats2bfloat162_rn(v.x - f01.x, v.y - f01.y);
    __nv_bfloat162 l23 = __floats2bfloat162_rn(v.z - f23.x, v.w - f23.y);
    uint2 uh, ul;
    uh.x = *reinterpret_cast<const uint32_t*>(&h01);
    uh.y = *reinterpret_cast<const uint32_t*>(&h23);
    ul.x = *reinterpret_cast<const uint32_t*>(&l01);
    ul.y = *reinterpret_cast<const uint32_t*>(&l23);
    hi[i] = uh;
    lo[i] = ul;
}

// ===========================================================================
// mma.sync GEMM:  C[M,N] = A[M,K] @ W[N,K]^T + bias[N]   (fp32 out)
// A, W given pre-split as bf16 hi/lo.  D = AhBh + AhBl + AlBh (fp32 accum).
// CTA tile 128x128, 8 warps (warp tile 32x64), K-chunk 32, FOUR-stage
// cp.async pipeline, one __syncthreads per chunk.
// Smem rows padded to 80B (conflict-free ldmatrix, 16B aligned).
// ===========================================================================
#define CH_K 32
#define NCHUNK (GK / CH_K)     // 32
#define NSTAGE 4
#define ROWB 80                // bytes per smem row (32 bf16 + 16B pad)
#define TSZ (128 * ROWB)       // 10240 bytes per tensor tile
#define STG (4 * TSZ)          // 40960 bytes per stage (Ahi,Alo,Bhi,Blo)
#define GSMEM (NSTAGE * STG)   // 163840 bytes

__device__ __forceinline__ uint32_t smem_u32(const void* p) {
    uint32_t a;
    asm("{ .reg .u64 t; cvta.to.shared.u64 t, %1; cvt.u32.u64 %0, t; }"
        : "=r"(a) : "l"(p));
    return a;
}

#define LDMX4(r, addr) \
    asm volatile("ldmatrix.sync.aligned.m8n8.x4.shared.b16 {%0,%1,%2,%3}, [%4];" \
        : "=r"((r)[0]), "=r"((r)[1]), "=r"((r)[2]), "=r"((r)[3]) : "r"(addr))

#define MMA16816(c, a, b0, b1) \
    asm volatile("mma.sync.aligned.m16n8k16.row.col.f32.bf16.bf16.f32 " \
        "{%0,%1,%2,%3}, {%4,%5,%6,%7}, {%8,%9}, {%0,%1,%2,%3};" \
        : "+f"((c)[0]), "+f"((c)[1]), "+f"((c)[2]), "+f"((c)[3]) \
        : "r"((a)[0]), "r"((a)[1]), "r"((a)[2]), "r"((a)[3]), "r"(b0), "r"(b1))

__global__ __launch_bounds__(256, 1)
void gemm_mma(const __nv_bfloat16* __restrict__ Ahi,
              const __nv_bfloat16* __restrict__ Alo,
              const __nv_bfloat16* __restrict__ Bhi,
              const __nv_bfloat16* __restrict__ Blo,
              const float* __restrict__ bias,
              float* __restrict__ C)
{
    extern __shared__ __align__(128) char smem[];
    const uint32_t sb = smem_u32(smem);
    const int tid = threadIdx.x;
    const int lane = tid & 31;
    const int wid = tid >> 5;
    const int warp_m = wid & 3;        // 4 warps along M (32 rows each)
    const int warp_n = wid >> 2;       // 2 warps along N (64 cols each)
    const int row0 = blockIdx.y * 128;
    const int col0 = blockIdx.x * 128;

    const __nv_bfloat16* gsrc[4];
    gsrc[0] = Ahi + (size_t)row0 * GK;
    gsrc[1] = Alo + (size_t)row0 * GK;
    gsrc[2] = Bhi + (size_t)col0 * GK;
    gsrc[3] = Blo + (size_t)col0 * GK;

    float acc[2][8][4];
#pragma unroll
    for (int mt = 0; mt < 2; mt++)
#pragma unroll
        for (int nt = 0; nt < 8; nt++)
#pragma unroll
            for (int j = 0; j < 4; j++)
                acc[mt][nt][j] = 0.0f;

#define ISSUE_STAGE(CH)                                                       \
    do {                                                                      \
        const int _k0 = (CH) * CH_K;                                          \
        const int _sg = (CH) & (NSTAGE - 1);                                  \
        _Pragma("unroll")                                                     \
        for (int _t = 0; _t < 4; _t++) {                                      \
            _Pragma("unroll")                                                 \
            for (int _j = 0; _j < 2; _j++) {                                  \
                int _idx = tid + _j * 256;     /* 0..511 */                   \
                int _r = _idx >> 2;            /* 0..127 */                   \
                int _c = _idx & 3;             /* 16B chunk in row */         \
                const __nv_bfloat16* _g = gsrc[_t] + (size_t)_r * GK + _k0 + _c * 8; \
                uint32_t _s = sb + _sg * STG + _t * TSZ + _r * ROWB + _c * 16; \
                asm volatile("cp.async.cg.shared.global [%0], [%1], 16;"      \
                             :: "r"(_s), "l"(_g));                            \
            }                                                                 \
        }                                                                     \
    } while (0)

    // Prologue: fill 3 of the 4 stages.
    ISSUE_STAGE(0);
    asm volatile("cp.async.commit_group;");
    ISSUE_STAGE(1);
    asm volatile("cp.async.commit_group;");
    ISSUE_STAGE(2);
    asm volatile("cp.async.commit_group;");

    for (int ch = 0; ch < NCHUNK; ch++) {
        // Own groups: ensure group `ch` is complete (<=2 newer pending).
        asm volatile("cp.async.wait_group 2;");
        __syncthreads();   // cross-thread visibility of stage ch

        const uint32_t stBase = sb + (ch & (NSTAGE - 1)) * STG;
#pragma unroll
        for (int ks = 0; ks < 2; ks++) {
            // --- A fragments: rows warp_m*32, two m16 tiles, hi & lo ---
            uint32_t a_hi[2][4], a_lo[2][4];
            {
                const uint32_t kb = (ks * 16 + (lane >> 4) * 8) * 2;
#pragma unroll
                for (int mt = 0; mt < 2; mt++) {
                    uint32_t ad = stBase
                                + (warp_m * 32 + mt * 16 + (lane & 15)) * ROWB + kb;
                    LDMX4(a_hi[mt], ad);
                    LDMX4(a_lo[mt], ad + TSZ);
                }
            }
            // --- B fragments per n16 pair; immediately consumed ---
#pragma unroll
            for (int pr = 0; pr < 4; pr++) {
                const uint32_t bd = stBase + 2 * TSZ
                    + (warp_n * 64 + pr * 16 + ((lane >> 4) & 1) * 8 + (lane & 7)) * ROWB
                    + (ks * 16 + ((lane >> 3) & 1) * 8) * 2;
                uint32_t b_hi[4], b_lo[4];
                LDMX4(b_hi, bd);
                LDMX4(b_lo, bd + TSZ);
#pragma unroll
                for (int mt = 0; mt < 2; mt++) {
                    MMA16816(acc[mt][2 * pr],     a_hi[mt], b_hi[0], b_hi[1]);
                    MMA16816(acc[mt][2 * pr],     a_hi[mt], b_lo[0], b_lo[1]);
                    MMA16816(acc[mt][2 * pr],     a_lo[mt], b_hi[0], b_hi[1]);
                    MMA16816(acc[mt][2 * pr + 1], a_hi[mt], b_hi[2], b_hi[3]);
                    MMA16816(acc[mt][2 * pr + 1], a_hi[mt], b_lo[2], b_lo[3]);
                    MMA16816(acc[mt][2 * pr + 1], a_lo[mt], b_hi[2], b_hi[3]);
                }
            }
        }

        // Prefetch chunk ch+3 into buffer (ch-1)&3.  Safe: the barrier above
        // proved all warps finished compute(ch-1).  Commit EVERY iteration
        // (empty group in the tail) so wait_group 2 stays uniform.
        if (ch + 3 < NCHUNK)
            ISSUE_STAGE(ch + 3);
        asm volatile("cp.async.commit_group;");
    }
#undef ISSUE_STAGE

    // Epilogue: mma c-fragment layout -> C with bias
#pragma unroll
    for (int mt = 0; mt < 2; mt++) {
        const int r = row0 + warp_m * 32 + mt * 16 + (lane >> 2);
#pragma unroll
        for (int nt = 0; nt < 8; nt++) {
            const int cc = col0 + warp_n * 64 + nt * 8 + (lane & 3) * 2;
            const float b0 = bias[cc], b1 = bias[cc + 1];
            float2 v0, v1;
            v0.x = acc[mt][nt][0] + b0;  v0.y = acc[mt][nt][1] + b1;
            v1.x = acc[mt][nt][2] + b0;  v1.y = acc[mt][nt][3] + b1;
            *(float2*)(C + (size_t)r * GN + cc) = v0;
            *(float2*)(C + (size_t)(r + 8) * GN + cc) = v1;
        }
    }
}

// ---------------------------------------------------------------------------
// Per-head dynamic-kernel conv; epilogue emits bf16 hi/lo split directly.
// ---------------------------------------------------------------------------
#define TOK_PER_BLK 32
#define TILE_ROWS (TOK_PER_BLK + 2 * PADMAX)   // 52

__global__ __launch_bounds__(256, 4)
void dka_conv_kernel(const float* __restrict__ xproj,
                     const float* __restrict__ Wc,
                     const float* __restrict__ A,
                     const float* __restrict__ V,
                     const float* __restrict__ base,
                     const float* __restrict__ alphas,
                     __nv_bfloat16* __restrict__ chi,
                     __nv_bfloat16* __restrict__ clo)
{
    __shared__ float xs[TILE_ROWS][DH];
    __shared__ float Wc_s[DH * RANK];
    __shared__ float A_s[RANK * KMAX];
    __shared__ float V_s[RANK * DH];
    __shared__ float base_s[KMAX * DH];

    const int tid  = threadIdx.x;
    const int lane = tid & 31;
    const int warp = tid >> 5;

    const int chunk = blockIdx.x;
    const int h     = blockIdx.y;
    const int b     = blockIdx.z;
    const int start = chunk * TOK_PER_BLK;

    const int KH   = (h < 2) ? 3 : (h < 4) ? 7 : (h < 6) ? 11 : 21;
    const int padH = KH >> 1;

    const float* xp_base = xproj + ((size_t)b * NTOK) * DMODEL + h * DH;
    for (int idx = tid; idx < TILE_ROWS * DH; idx += 256) {
        int row = idx >> 7;
        int col = idx & 127;
        int gn  = start - PADMAX + row;
        float v = 0.0f;
        if (gn >= 0 && gn < NTOK)
            v = xp_base[(size_t)gn * DMODEL + col];
        xs[row][col] = v;
    }
    for (int idx = tid; idx < DH * RANK; idx += 256)
        Wc_s[idx] = Wc[(size_t)h * DH * RANK + idx];
    for (int idx = tid; idx < RANK * KMAX; idx += 256)
        A_s[idx] = A[(size_t)h * RANK * KMAX + idx];
    for (int idx = tid; idx < RANK * DH; idx += 256)
        V_s[idx] = V[(size_t)h * RANK * DH + idx];
    for (int idx = tid; idx < KMAX * DH; idx += 256)
        base_s[idx] = base[(size_t)h * KMAX * DH + idx];
    __syncthreads();

    const float alpha = 1.0f / (1.0f + __expf(-alphas[h]));
    const float oma   = 1.0f - alpha;

    for (int it = 0; it < TOK_PER_BLK / 8; it++) {
        const int lt     = warp + 8 * it;
        const int center = lt + PADMAX;

        float xv[4];
#pragma unroll
        for (int i = 0; i < 4; i++)
            xv[i] = xs[center][lane + 32 * i];

        float c0 = 0.f, c1 = 0.f, c2 = 0.f, c3 = 0.f;
#pragma unroll
        for (int i = 0; i < 4; i++) {
            int d = lane + 32 * i;
            float x = xv[i];
            c0 = fmaf(x, Wc_s[d * RANK + 0], c0);
            c1 = fmaf(x, Wc_s[d * RANK + 1], c1);
            c2 = fmaf(x, Wc_s[d * RANK + 2], c2);
            c3 = fmaf(x, Wc_s[d * RANK + 3], c3);
        }
#pragma unroll
        for (int off = 16; off > 0; off >>= 1) {
            c0 += __shfl_xor_sync(0xffffffffu, c0, off);
            c1 += __shfl_xor_sync(0xffffffffu, c1, off);
            c2 += __shfl_xor_sync(0xffffffffu, c2, off);
            c3 += __shfl_xor_sync(0xffffffffu, c3, off);
        }

        float acc[4] = {0.f, 0.f, 0.f, 0.f};
        for (int k = 0; k < KH; k++) {
            const float ca0 = c0 * A_s[0 * KMAX + k];
            const float ca1 = c1 * A_s[1 * KMAX + k];
            const float ca2 = c2 * A_s[2 * KMAX + k];
            const float ca3 = c3 * A_s[3 * KMAX + k];
            const int row = center - padH + k;
#pragma unroll
            for (int i = 0; i < 4; i++) {
                int d = lane + 32 * i;
                float dyn = ca0 * V_s[0 * DH + d]
                          + ca1 * V_s[1 * DH + d]
                          + ca2 * V_s[2 * DH + d]
                          + ca3 * V_s[3 * DH + d];
                float kh = alpha * dyn + oma * base_s[k * DH + d];
                acc[i] = fmaf(kh, xs[row][d], acc[i]);
            }
        }

        const int n = start + lt;
        const size_t ob = ((size_t)b * NTOK + n) * DMODEL + h * DH;
#pragma unroll
        for (int i = 0; i < 4; i++) {
            float a = acc[i];
            __nv_bfloat16 hbf = __float2bfloat16(a);
            float hf = __bfloat162float(hbf);
            chi[ob + lane + 32 * i] = hbf;
            clo[ob + lane + 32 * i] = __float2bfloat16(a - hf);
        }
    }
}

// ---------------------------------------------------------------------------
// Launch
// ---------------------------------------------------------------------------
extern "C" void kernel_launch(void* const* d_in, const int* in_sizes, int n_in,
                              void* d_out, int out_size)
{
    const float* x      = (const float*)d_in[0];
    const float* W_in   = (const float*)d_in[1];
    const float* b_in   = (const float*)d_in[2];
    const float* W_out  = (const float*)d_in[3];
    const float* b_out  = (const float*)d_in[4];
    const float* Wc     = (const float*)d_in[5];
    const float* A      = (const float*)d_in[6];
    const float* V      = (const float*)d_in[7];
    const float* base   = (const float*)d_in[8];
    const float* alphas = (const float*)d_in[9];
    float* out = (float*)d_out;

    float* xproj; cudaGetSymbolAddress((void**)&xproj, g_xproj);
    __nv_bfloat16 *xhi, *xlo, *chi, *clo, *wih, *wil, *woh, *wol;
    cudaGetSymbolAddress((void**)&xhi, g_xhi);
    cudaGetSymbolAddress((void**)&xlo, g_xlo);
    cudaGetSymbolAddress((void**)&chi, g_chi);
    cudaGetSymbolAddress((void**)&clo, g_clo);
    cudaGetSymbolAddress((void**)&wih, g_wih);
    cudaGetSymbolAddress((void**)&wil, g_wil);
    cudaGetSymbolAddress((void**)&woh, g_woh);
    cudaGetSymbolAddress((void**)&wol, g_wol);

    cudaFuncSetAttribute(gemm_mma, cudaFuncAttributeMaxDynamicSharedMemorySize, GSMEM);

    // Splits
    {
        int n4x = GM * GK / 4;          // 2,097,152
        split_bf16<<<(n4x + 255) / 256, 256>>>((const float4*)x,
            (uint2*)xhi, (uint2*)xlo, n4x);
        int n4w = GN * GK / 4;          // 262,144
        split_bf16<<<(n4w + 255) / 256, 256>>>((const float4*)W_in,
            (uint2*)wih, (uint2*)wil, n4w);
        split_bf16<<<(n4w + 255) / 256, 256>>>((const float4*)W_out,
            (uint2*)woh, (uint2*)wol, n4w);
    }
    // GEMM1: xproj = x @ W_in^T + b_in
    {
        dim3 grid(GN / 128, GM / 128);   // (8, 64)
        gemm_mma<<<grid, 256, GSMEM>>>(xhi, xlo, wih, wil, b_in, xproj);
    }
    // Per-head dynamic conv -> concat (bf16 hi/lo)
    {
        dim3 grid(NTOK / TOK_PER_BLK, NHEADS, Bsz);
        dka_conv_kernel<<<grid, 256>>>(xproj, Wc, A, V, base, alphas, chi, clo);
    }
    // GEMM2: out = concat @ W_out^T + b_out
    {
        dim3 grid(GN / 128, GM / 128);
        gemm_mma<<<grid, 256, GSMEM>>>(chi, clo, woh, wol, b_out, out);
    }
}

// round 9
// speedup vs baseline: 2.3212x; 1.0047x over previous
#include <cuda_runtime.h>
#include <cuda_bf16.h>
#include <cstdint>
#include <math.h>

// Problem constants
#define Bsz 2
#define NTOK 4096
#define DMODEL 1024
#define NHEADS 8
#define DH 128
#define RANK 4
#define KMAX 21
#define PADMAX 10   // KMAX/2

#define GM (Bsz * NTOK)   // 8192
#define GK DMODEL         // 1024
#define GN DMODEL         // 1024

// Scratch (device globals; runtime allocation is forbidden)
__device__ float g_xproj[GM * GK];                 // x @ W_in.T + b_in (fp32 for conv)
__device__ __nv_bfloat16 g_xhi[GM * GK];           // split of x
__device__ __nv_bfloat16 g_xlo[GM * GK];
__device__ __nv_bfloat16 g_chi[GM * GK];           // split of concat (written by conv)
__device__ __nv_bfloat16 g_clo[GM * GK];
__device__ __nv_bfloat16 g_wih[GN * GK];           // split of W_in
__device__ __nv_bfloat16 g_wil[GN * GK];
__device__ __nv_bfloat16 g_woh[GN * GK];           // split of W_out
__device__ __nv_bfloat16 g_wol[GN * GK];

// ===========================================================================
// Elementwise fp32 -> (bf16 hi, bf16 lo) split.  n4 = element count / 4.
// ===========================================================================
__global__ __launch_bounds__(256)
void split_bf16(const float4* __restrict__ in, uint2* __restrict__ hi,
                uint2* __restrict__ lo, int n4)
{
    int i = blockIdx.x * 256 + threadIdx.x;
    if (i >= n4) return;
    float4 v = in[i];
    __nv_bfloat162 h01 = __floats2bfloat162_rn(v.x, v.y);
    __nv_bfloat162 h23 = __floats2bfloat162_rn(v.z, v.w);
    float2 f01 = __bfloat1622float2(h01);
    float2 f23 = __bfloat1622float2(h23);
    __nv_bfloat162 l01 = __floats2bfloat162_rn(v.x - f01.x, v.y - f01.y);
    __nv_bfloat162 l23 = __floats2bfloat162_rn(v.z - f23.x, v.w - f23.y);
    uint2 uh, ul;
    uh.x = *reinterpret_cast<const uint32_t*>(&h01);
    uh.y = *reinterpret_cast<const uint32_t*>(&h23);
    ul.x = *reinterpret_cast<const uint32_t*>(&l01);
    ul.y = *reinterpret_cast<const uint32_t*>(&l23);
    hi[i] = uh;
    lo[i] = ul;
}

// ===========================================================================
// mma.sync GEMM:  C[M,N] = A[M,K] @ W[N,K]^T + bias[N]   (fp32 out)
// A, W given pre-split as bf16 hi/lo.  D = AhBh + AhBl + AlBh (fp32 accum).
// CTA tile 128x128, 8 warps (warp tile 32x64), K-chunk 64, THREE-stage
// cp.async pipeline, one __syncthreads per chunk, prefetch issued before
// compute.  Smem rows padded to 144B (128B payload): row stride mod 32
// banks = 4 -> 8 consecutive ldmatrix rows hit distinct banks.
// ===========================================================================
#define CH_K 64
#define NCHUNK (GK / CH_K)     // 16
#define NSTAGE 3
#define ROWB 144               // bytes per smem row (64 bf16 + 16B pad)
#define TSZ (128 * ROWB)       // 18432 bytes per tensor tile
#define STG (4 * TSZ)          // 73728 bytes per stage (Ahi,Alo,Bhi,Blo)
#define GSMEM (NSTAGE * STG)   // 221184 bytes

__device__ __forceinline__ uint32_t smem_u32(const void* p) {
    uint32_t a;
    asm("{ .reg .u64 t; cvta.to.shared.u64 t, %1; cvt.u32.u64 %0, t; }"
        : "=r"(a) : "l"(p));
    return a;
}

#define LDMX4(r, addr) \
    asm volatile("ldmatrix.sync.aligned.m8n8.x4.shared.b16 {%0,%1,%2,%3}, [%4];" \
        : "=r"((r)[0]), "=r"((r)[1]), "=r"((r)[2]), "=r"((r)[3]) : "r"(addr))

#define MMA16816(c, a, b0, b1) \
    asm volatile("mma.sync.aligned.m16n8k16.row.col.f32.bf16.bf16.f32 " \
        "{%0,%1,%2,%3}, {%4,%5,%6,%7}, {%8,%9}, {%0,%1,%2,%3};" \
        : "+f"((c)[0]), "+f"((c)[1]), "+f"((c)[2]), "+f"((c)[3]) \
        : "r"((a)[0]), "r"((a)[1]), "r"((a)[2]), "r"((a)[3]), "r"(b0), "r"(b1))

__global__ __launch_bounds__(256, 1)
void gemm_mma(const __nv_bfloat16* __restrict__ Ahi,
              const __nv_bfloat16* __restrict__ Alo,
              const __nv_bfloat16* __restrict__ Bhi,
              const __nv_bfloat16* __restrict__ Blo,
              const float* __restrict__ bias,
              float* __restrict__ C)
{
    extern __shared__ __align__(128) char smem[];
    const uint32_t sb = smem_u32(smem);
    const int tid = threadIdx.x;
    const int lane = tid & 31;
    const int wid = tid >> 5;
    const int warp_m = wid & 3;        // 4 warps along M (32 rows each)
    const int warp_n = wid >> 2;       // 2 warps along N (64 cols each)
    const int row0 = blockIdx.y * 128;
    const int col0 = blockIdx.x * 128;

    const __nv_bfloat16* gsrc[4];
    gsrc[0] = Ahi + (size_t)row0 * GK;
    gsrc[1] = Alo + (size_t)row0 * GK;
    gsrc[2] = Bhi + (size_t)col0 * GK;
    gsrc[3] = Blo + (size_t)col0 * GK;

    float acc[2][8][4];
#pragma unroll
    for (int mt = 0; mt < 2; mt++)
#pragma unroll
        for (int nt = 0; nt < 8; nt++)
#pragma unroll
            for (int j = 0; j < 4; j++)
                acc[mt][nt][j] = 0.0f;

    // Per stage: 4 tensors x 128 rows x 8 chunks(16B) = 4096 chunks;
    // 256 threads -> 16 chunks each (4 per tensor).
#define ISSUE_STAGE(CH)                                                       \
    do {                                                                      \
        const int _k0 = (CH) * CH_K;                                          \
        const uint32_t _sbase = sb + ((CH) % NSTAGE) * STG;                   \
        _Pragma("unroll")                                                     \
        for (int _t = 0; _t < 4; _t++) {                                      \
            _Pragma("unroll")                                                 \
            for (int _j = 0; _j < 4; _j++) {                                  \
                int _idx = tid + _j * 256;     /* 0..1023 */                  \
                int _r = _idx >> 3;            /* 0..127 */                   \
                int _c = _idx & 7;             /* 16B chunk in row */         \
                const __nv_bfloat16* _g = gsrc[_t] + (size_t)_r * GK + _k0 + _c * 8; \
                uint32_t _s = _sbase + _t * TSZ + _r * ROWB + _c * 16;        \
                asm volatile("cp.async.cg.shared.global [%0], [%1], 16;"      \
                             :: "r"(_s), "l"(_g));                            \
            }                                                                 \
        }                                                                     \
    } while (0)

    // Prologue: fill 2 of the 3 stages.
    ISSUE_STAGE(0);
    asm volatile("cp.async.commit_group;");
    ISSUE_STAGE(1);
    asm volatile("cp.async.commit_group;");

    for (int ch = 0; ch < NCHUNK; ch++) {
        // Group ch complete (<=1 newer pending).
        asm volatile("cp.async.wait_group 1;");
        __syncthreads();   // cross-thread visibility of stage ch; also proves
                           // all warps done computing stage ch-1.

        // Prefetch ch+2 into buffer (ch+2)%3 == (ch-1)%3 — safe per barrier.
        // Issued BEFORE compute so the loads overlap this chunk's MMAs.
        if (ch + 2 < NCHUNK)
            ISSUE_STAGE(ch + 2);
        asm volatile("cp.async.commit_group;");

        const uint32_t stBase = sb + (ch % NSTAGE) * STG;
#pragma unroll
        for (int ks = 0; ks < 4; ks++) {
            // --- A fragments: rows warp_m*32, two m16 tiles, hi & lo ---
            uint32_t a_hi[2][4], a_lo[2][4];
            {
                const uint32_t kb = (ks * 16 + (lane >> 4) * 8) * 2;
#pragma unroll
                for (int mt = 0; mt < 2; mt++) {
                    uint32_t ad = stBase
                                + (warp_m * 32 + mt * 16 + (lane & 15)) * ROWB + kb;
                    LDMX4(a_hi[mt], ad);
                    LDMX4(a_lo[mt], ad + TSZ);
                }
            }
            // --- B fragments per n16 pair; immediately consumed ---
#pragma unroll
            for (int pr = 0; pr < 4; pr++) {
                const uint32_t bd = stBase + 2 * TSZ
                    + (warp_n * 64 + pr * 16 + ((lane >> 4) & 1) * 8 + (lane & 7)) * ROWB
                    + (ks * 16 + ((lane >> 3) & 1) * 8) * 2;
                uint32_t b_hi[4], b_lo[4];
                LDMX4(b_hi, bd);
                LDMX4(b_lo, bd + TSZ);
#pragma unroll
                for (int mt = 0; mt < 2; mt++) {
                    MMA16816(acc[mt][2 * pr],     a_hi[mt], b_hi[0], b_hi[1]);
                    MMA16816(acc[mt][2 * pr],     a_hi[mt], b_lo[0], b_lo[1]);
                    MMA16816(acc[mt][2 * pr],     a_lo[mt], b_hi[0], b_hi[1]);
                    MMA16816(acc[mt][2 * pr + 1], a_hi[mt], b_hi[2], b_hi[3]);
                    MMA16816(acc[mt][2 * pr + 1], a_hi[mt], b_lo[2], b_lo[3]);
                    MMA16816(acc[mt][2 * pr + 1], a_lo[mt], b_hi[2], b_hi[3]);
                }
            }
        }
    }
#undef ISSUE_STAGE

    // Epilogue: mma c-fragment layout -> C with bias
#pragma unroll
    for (int mt = 0; mt < 2; mt++) {
        const int r = row0 + warp_m * 32 + mt * 16 + (lane >> 2);
#pragma unroll
        for (int nt = 0; nt < 8; nt++) {
            const int cc = col0 + warp_n * 64 + nt * 8 + (lane & 3) * 2;
            const float b0 = bias[cc], b1 = bias[cc + 1];
            float2 v0, v1;
            v0.x = acc[mt][nt][0] + b0;  v0.y = acc[mt][nt][1] + b1;
            v1.x = acc[mt][nt][2] + b0;  v1.y = acc[mt][nt][3] + b1;
            *(float2*)(C + (size_t)r * GN + cc) = v0;
            *(float2*)(C + (size_t)(r + 8) * GN + cc) = v1;
        }
    }
}

// ---------------------------------------------------------------------------
// Per-head dynamic-kernel conv; epilogue emits bf16 hi/lo split directly.
// ---------------------------------------------------------------------------
#define TOK_PER_BLK 32
#define TILE_ROWS (TOK_PER_BLK + 2 * PADMAX)   // 52

__global__ __launch_bounds__(256, 4)
void dka_conv_kernel(const float* __restrict__ xproj,
                     const float* __restrict__ Wc,
                     const float* __restrict__ A,
                     const float* __restrict__ V,
                     const float* __restrict__ base,
                     const float* __restrict__ alphas,
                     __nv_bfloat16* __restrict__ chi,
                     __nv_bfloat16* __restrict__ clo)
{
    __shared__ float xs[TILE_ROWS][DH];
    __shared__ float Wc_s[DH * RANK];
    __shared__ float A_s[RANK * KMAX];
    __shared__ float V_s[RANK * DH];
    __shared__ float base_s[KMAX * DH];

    const int tid  = threadIdx.x;
    const int lane = tid & 31;
    const int warp = tid >> 5;

    const int chunk = blockIdx.x;
    const int h     = blockIdx.y;
    const int b     = blockIdx.z;
    const int start = chunk * TOK_PER_BLK;

    const int KH   = (h < 2) ? 3 : (h < 4) ? 7 : (h < 6) ? 11 : 21;
    const int padH = KH >> 1;

    const float* xp_base = xproj + ((size_t)b * NTOK) * DMODEL + h * DH;
    for (int idx = tid; idx < TILE_ROWS * DH; idx += 256) {
        int row = idx >> 7;
        int col = idx & 127;
        int gn  = start - PADMAX + row;
        float v = 0.0f;
        if (gn >= 0 && gn < NTOK)
            v = xp_base[(size_t)gn * DMODEL + col];
        xs[row][col] = v;
    }
    for (int idx = tid; idx < DH * RANK; idx += 256)
        Wc_s[idx] = Wc[(size_t)h * DH * RANK + idx];
    for (int idx = tid; idx < RANK * KMAX; idx += 256)
        A_s[idx] = A[(size_t)h * RANK * KMAX + idx];
    for (int idx = tid; idx < RANK * DH; idx += 256)
        V_s[idx] = V[(size_t)h * RANK * DH + idx];
    for (int idx = tid; idx < KMAX * DH; idx += 256)
        base_s[idx] = base[(size_t)h * KMAX * DH + idx];
    __syncthreads();

    const float alpha = 1.0f / (1.0f + __expf(-alphas[h]));
    const float oma   = 1.0f - alpha;

    for (int it = 0; it < TOK_PER_BLK / 8; it++) {
        const int lt     = warp + 8 * it;
        const int center = lt + PADMAX;

        float xv[4];
#pragma unroll
        for (int i = 0; i < 4; i++)
            xv[i] = xs[center][lane + 32 * i];

        float c0 = 0.f, c1 = 0.f, c2 = 0.f, c3 = 0.f;
#pragma unroll
        for (int i = 0; i < 4; i++) {
            int d = lane + 32 * i;
            float x = xv[i];
            c0 = fmaf(x, Wc_s[d * RANK + 0], c0);
            c1 = fmaf(x, Wc_s[d * RANK + 1], c1);
            c2 = fmaf(x, Wc_s[d * RANK + 2], c2);
            c3 = fmaf(x, Wc_s[d * RANK + 3], c3);
        }
#pragma unroll
        for (int off = 16; off > 0; off >>= 1) {
            c0 += __shfl_xor_sync(0xffffffffu, c0, off);
            c1 += __shfl_xor_sync(0xffffffffu, c1, off);
            c2 += __shfl_xor_sync(0xffffffffu, c2, off);
            c3 += __shfl_xor_sync(0xffffffffu, c3, off);
        }

        float acc[4] = {0.f, 0.f, 0.f, 0.f};
        for (int k = 0; k < KH; k++) {
            const float ca0 = c0 * A_s[0 * KMAX + k];
            const float ca1 = c1 * A_s[1 * KMAX + k];
            const float ca2 = c2 * A_s[2 * KMAX + k];
            const float ca3 = c3 * A_s[3 * KMAX + k];
            const int row = center - padH + k;
#pragma unroll
            for (int i = 0; i < 4; i++) {
                int d = lane + 32 * i;
                float dyn = ca0 * V_s[0 * DH + d]
                          + ca1 * V_s[1 * DH + d]
                          + ca2 * V_s[2 * DH + d]
                          + ca3 * V_s[3 * DH + d];
                float kh = alpha * dyn + oma * base_s[k * DH + d];
                acc[i] = fmaf(kh, xs[row][d], acc[i]);
            }
        }

        const int n = start + lt;
        const size_t ob = ((size_t)b * NTOK + n) * DMODEL + h * DH;
#pragma unroll
        for (int i = 0; i < 4; i++) {
            float a = acc[i];
            __nv_bfloat16 hbf = __float2bfloat16(a);
            float hf = __bfloat162float(hbf);
            chi[ob + lane + 32 * i] = hbf;
            clo[ob + lane + 32 * i] = __float2bfloat16(a - hf);
        }
    }
}

// ---------------------------------------------------------------------------
// Launch
// ---------------------------------------------------------------------------
extern "C" void kernel_launch(void* const* d_in, const int* in_sizes, int n_in,
                              void* d_out, int out_size)
{
    const float* x      = (const float*)d_in[0];
    const float* W_in   = (const float*)d_in[1];
    const float* b_in   = (const float*)d_in[2];
    const float* W_out  = (const float*)d_in[3];
    const float* b_out  = (const float*)d_in[4];
    const float* Wc     = (const float*)d_in[5];
    const float* A      = (const float*)d_in[6];
    const float* V      = (const float*)d_in[7];
    const float* base   = (const float*)d_in[8];
    const float* alphas = (const float*)d_in[9];
    float* out = (float*)d_out;

    float* xproj; cudaGetSymbolAddress((void**)&xproj, g_xproj);
    __nv_bfloat16 *xhi, *xlo, *chi, *clo, *wih, *wil, *woh, *wol;
    cudaGetSymbolAddress((void**)&xhi, g_xhi);
    cudaGetSymbolAddress((void**)&xlo, g_xlo);
    cudaGetSymbolAddress((void**)&chi, g_chi);
    cudaGetSymbolAddress((void**)&clo, g_clo);
    cudaGetSymbolAddress((void**)&wih, g_wih);
    cudaGetSymbolAddress((void**)&wil, g_wil);
    cudaGetSymbolAddress((void**)&woh, g_woh);
    cudaGetSymbolAddress((void**)&wol, g_wol);

    cudaFuncSetAttribute(gemm_mma, cudaFuncAttributeMaxDynamicSharedMemorySize, GSMEM);

    // Splits
    {
        int n4x = GM * GK / 4;          // 2,097,152
        split_bf16<<<(n4x + 255) / 256, 256>>>((const float4*)x,
            (uint2*)xhi, (uint2*)xlo, n4x);
        int n4w = GN * GK / 4;          // 262,144
        split_bf16<<<(n4w + 255) / 256, 256>>>((const float4*)W_in,
            (uint2*)wih, (uint2*)wil, n4w);
        split_bf16<<<(n4w + 255) / 256, 256>>>((const float4*)W_out,
            (uint2*)woh, (uint2*)wol, n4w);
    }
    // GEMM1: xproj = x @ W_in^T + b_in
    {
        dim3 grid(GN / 128, GM / 128);   // (8, 64)
        gemm_mma<<<grid, 256, GSMEM>>>(xhi, xlo, wih, wil, b_in, xproj);
    }
    // Per-head dynamic conv -> concat (bf16 hi/lo)
    {
        dim3 grid(NTOK / TOK_PER_BLK, NHEADS, Bsz);
        dka_conv_kernel<<<grid, 256>>>(xproj, Wc, A, V, base, alphas, chi, clo);
    }
    // GEMM2: out = concat @ W_out^T + b_out
    {
        dim3 grid(GN / 128, GM / 128);
        gemm_mma<<<grid, 256, GSMEM>>>(chi, clo, woh, wol, b_out, out);
    }
}

// round 10
// speedup vs baseline: 2.4196x; 1.0424x over previous
#include <cuda_runtime.h>
#include <cuda_bf16.h>
#include <cstdint>
#include <math.h>

// Problem constants
#define Bsz 2
#define NTOK 4096
#define DMODEL 1024
#define NHEADS 8
#define DH 128
#define RANK 4
#define KMAX 21
#define PADMAX 10   // KMAX/2

#define GM (Bsz * NTOK)   // 8192
#define GK DMODEL         // 1024
#define GN DMODEL         // 1024

// Scratch (device globals; runtime allocation is forbidden)
__device__ float g_xproj[GM * GK];                 // x @ W_in.T + b_in (fp32 for conv)
__device__ __nv_bfloat16 g_xhi[GM * GK];           // split of x
__device__ __nv_bfloat16 g_xlo[GM * GK];
__device__ __nv_bfloat16 g_chi[GM * GK];           // split of concat (written by conv)
__device__ __nv_bfloat16 g_clo[GM * GK];
__device__ __nv_bfloat16 g_wih[GN * GK];           // split of W_in
__device__ __nv_bfloat16 g_wil[GN * GK];
__device__ __nv_bfloat16 g_woh[GN * GK];           // split of W_out
__device__ __nv_bfloat16 g_wol[GN * GK];

// ===========================================================================
// Elementwise fp32 -> (bf16 hi, bf16 lo) split.  n4 = element count / 4.
// ===========================================================================
__global__ __launch_bounds__(256)
void split_bf16(const float4* __restrict__ in, uint2* __restrict__ hi,
                uint2* __restrict__ lo, int n4)
{
    int i = blockIdx.x * 256 + threadIdx.x;
    if (i >= n4) return;
    float4 v = in[i];
    __nv_bfloat162 h01 = __floats2bfloat162_rn(v.x, v.y);
    __nv_bfloat162 h23 = __floats2bfloat162_rn(v.z, v.w);
    float2 f01 = __bfloat1622float2(h01);
    float2 f23 = __bfloat1622float2(h23);
    __nv_bfloat162 l01 = __floats2bfloat162_rn(v.x - f01.x, v.y - f01.y);
    __nv_bfloat162 l23 = __floats2bfloat162_rn(v.z - f23.x, v.w - f23.y);
    uint2 uh, ul;
    uh.x = *reinterpret_cast<const uint32_t*>(&h01);
    uh.y = *reinterpret_cast<const uint32_t*>(&h23);
    ul.x = *reinterpret_cast<const uint32_t*>(&l01);
    ul.y = *reinterpret_cast<const uint32_t*>(&l23);
    hi[i] = uh;
    lo[i] = ul;
}

// ===========================================================================
// mma.sync GEMM:  C[M,N] = A[M,K] @ W[N,K]^T + bias[N]   (fp32 out)
// A, W given pre-split as bf16 hi/lo.  D = AhBh + AhBl + AlBh (fp32 accum).
// CTA tile 128x128, 8 warps (warp tile 32x64), K-chunk 32, TWO-stage
// cp.async pipeline, one __syncthreads per chunk, TWO CTAs PER SM
// (launch_bounds(256,2) -> regs<=128; smem 2x81920=160KB of 227KB).
// Smem rows padded to 80B (conflict-free ldmatrix, 16B aligned).
// ===========================================================================
#define CH_K 32
#define NCHUNK (GK / CH_K)     // 32
#define NSTAGE 2
#define ROWB 80                // bytes per smem row (32 bf16 + 16B pad)
#define TSZ (128 * ROWB)       // 10240 bytes per tensor tile
#define STG (4 * TSZ)          // 40960 bytes per stage (Ahi,Alo,Bhi,Blo)
#define GSMEM (NSTAGE * STG)   // 81920 bytes

__device__ __forceinline__ uint32_t smem_u32(const void* p) {
    uint32_t a;
    asm("{ .reg .u64 t; cvta.to.shared.u64 t, %1; cvt.u32.u64 %0, t; }"
        : "=r"(a) : "l"(p));
    return a;
}

#define LDMX4(r, addr) \
    asm volatile("ldmatrix.sync.aligned.m8n8.x4.shared.b16 {%0,%1,%2,%3}, [%4];" \
        : "=r"((r)[0]), "=r"((r)[1]), "=r"((r)[2]), "=r"((r)[3]) : "r"(addr))

#define MMA16816(c, a, b0, b1) \
    asm volatile("mma.sync.aligned.m16n8k16.row.col.f32.bf16.bf16.f32 " \
        "{%0,%1,%2,%3}, {%4,%5,%6,%7}, {%8,%9}, {%0,%1,%2,%3};" \
        : "+f"((c)[0]), "+f"((c)[1]), "+f"((c)[2]), "+f"((c)[3]) \
        : "r"((a)[0]), "r"((a)[1]), "r"((a)[2]), "r"((a)[3]), "r"(b0), "r"(b1))

__global__ __launch_bounds__(256, 2)
void gemm_mma(const __nv_bfloat16* __restrict__ Ahi,
              const __nv_bfloat16* __restrict__ Alo,
              const __nv_bfloat16* __restrict__ Bhi,
              const __nv_bfloat16* __restrict__ Blo,
              const float* __restrict__ bias,
              float* __restrict__ C)
{
    extern __shared__ __align__(128) char smem[];
    const uint32_t sb = smem_u32(smem);
    const int tid = threadIdx.x;
    const int lane = tid & 31;
    const int wid = tid >> 5;
    const int warp_m = wid & 3;        // 4 warps along M (32 rows each)
    const int warp_n = wid >> 2;       // 2 warps along N (64 cols each)
    const int row0 = blockIdx.y * 128;
    const int col0 = blockIdx.x * 128;

    const __nv_bfloat16* gsrc[4];
    gsrc[0] = Ahi + (size_t)row0 * GK;
    gsrc[1] = Alo + (size_t)row0 * GK;
    gsrc[2] = Bhi + (size_t)col0 * GK;
    gsrc[3] = Blo + (size_t)col0 * GK;

    float acc[2][8][4];
#pragma unroll
    for (int mt = 0; mt < 2; mt++)
#pragma unroll
        for (int nt = 0; nt < 8; nt++)
#pragma unroll
            for (int j = 0; j < 4; j++)
                acc[mt][nt][j] = 0.0f;

    // Per stage: 4 tensors x 128 rows x 4 chunks(16B) = 2048 chunks;
    // 256 threads -> 8 chunks each (2 per tensor).
#define ISSUE_STAGE(CH)                                                       \
    do {                                                                      \
        const int _k0 = (CH) * CH_K;                                          \
        const uint32_t _sbase = sb + ((CH) & 1) * STG;                        \
        _Pragma("unroll")                                                     \
        for (int _t = 0; _t < 4; _t++) {                                      \
            _Pragma("unroll")                                                 \
            for (int _j = 0; _j < 2; _j++) {                                  \
                int _idx = tid + _j * 256;     /* 0..511 */                   \
                int _r = _idx >> 2;            /* 0..127 */                   \
                int _c = _idx & 3;             /* 16B chunk in row */         \
                const __nv_bfloat16* _g = gsrc[_t] + (size_t)_r * GK + _k0 + _c * 8; \
                uint32_t _s = _sbase + _t * TSZ + _r * ROWB + _c * 16;        \
                asm volatile("cp.async.cg.shared.global [%0], [%1], 16;"      \
                             :: "r"(_s), "l"(_g));                            \
            }                                                                 \
        }                                                                     \
        asm volatile("cp.async.commit_group;");                               \
    } while (0)

    ISSUE_STAGE(0);

    for (int ch = 0; ch < NCHUNK; ch++) {
        // Wait for ALL pending groups (== group ch).
        asm volatile("cp.async.wait_group 0;");
        __syncthreads();   // stage ch visible to all; all warps done ch-1.

        // Prefetch ch+1 into the other buffer; overlaps this chunk's MMAs.
        if (ch + 1 < NCHUNK)
            ISSUE_STAGE(ch + 1);

        const uint32_t stBase = sb + (ch & 1) * STG;
#pragma unroll
        for (int ks = 0; ks < 2; ks++) {
            // --- A fragments: rows warp_m*32, two m16 tiles, hi & lo ---
            uint32_t a_hi[2][4], a_lo[2][4];
            {
                const uint32_t kb = (ks * 16 + (lane >> 4) * 8) * 2;
#pragma unroll
                for (int mt = 0; mt < 2; mt++) {
                    uint32_t ad = stBase
                                + (warp_m * 32 + mt * 16 + (lane & 15)) * ROWB + kb;
                    LDMX4(a_hi[mt], ad);
                    LDMX4(a_lo[mt], ad + TSZ);
                }
            }
            // --- B fragments per n16 pair; immediately consumed ---
#pragma unroll
            for (int pr = 0; pr < 4; pr++) {
                const uint32_t bd = stBase + 2 * TSZ
                    + (warp_n * 64 + pr * 16 + ((lane >> 4) & 1) * 8 + (lane & 7)) * ROWB
                    + (ks * 16 + ((lane >> 3) & 1) * 8) * 2;
                uint32_t b_hi[4], b_lo[4];
                LDMX4(b_hi, bd);
                LDMX4(b_lo, bd + TSZ);
                // Interleave across 4 independent accumulators to break
                // same-accumulator RAW chains.
#pragma unroll
                for (int mt = 0; mt < 2; mt++) {
                    MMA16816(acc[mt][2 * pr],     a_hi[mt], b_hi[0], b_hi[1]);
                    MMA16816(acc[mt][2 * pr + 1], a_hi[mt], b_hi[2], b_hi[3]);
                }
#pragma unroll
                for (int mt = 0; mt < 2; mt++) {
                    MMA16816(acc[mt][2 * pr],     a_hi[mt], b_lo[0], b_lo[1]);
                    MMA16816(acc[mt][2 * pr + 1], a_hi[mt], b_lo[2], b_lo[3]);
                }
#pragma unroll
                for (int mt = 0; mt < 2; mt++) {
                    MMA16816(acc[mt][2 * pr],     a_lo[mt], b_hi[0], b_hi[1]);
                    MMA16816(acc[mt][2 * pr + 1], a_lo[mt], b_hi[2], b_hi[3]);
                }
            }
        }
    }
#undef ISSUE_STAGE

    // Epilogue: mma c-fragment layout -> C with bias
#pragma unroll
    for (int mt = 0; mt < 2; mt++) {
        const int r = row0 + warp_m * 32 + mt * 16 + (lane >> 2);
#pragma unroll
        for (int nt = 0; nt < 8; nt++) {
            const int cc = col0 + warp_n * 64 + nt * 8 + (lane & 3) * 2;
            const float b0 = bias[cc], b1 = bias[cc + 1];
            float2 v0, v1;
            v0.x = acc[mt][nt][0] + b0;  v0.y = acc[mt][nt][1] + b1;
            v1.x = acc[mt][nt][2] + b0;  v1.y = acc[mt][nt][3] + b1;
            *(float2*)(C + (size_t)r * GN + cc) = v0;
            *(float2*)(C + (size_t)(r + 8) * GN + cc) = v1;
        }
    }
}

// ---------------------------------------------------------------------------
// Per-head dynamic-kernel conv; epilogue emits bf16 hi/lo split directly.
// ---------------------------------------------------------------------------
#define TOK_PER_BLK 32
#define TILE_ROWS (TOK_PER_BLK + 2 * PADMAX)   // 52

__global__ __launch_bounds__(256, 4)
void dka_conv_kernel(const float* __restrict__ xproj,
                     const float* __restrict__ Wc,
                     const float* __restrict__ A,
                     const float* __restrict__ V,
                     const float* __restrict__ base,
                     const float* __restrict__ alphas,
                     __nv_bfloat16* __restrict__ chi,
                     __nv_bfloat16* __restrict__ clo)
{
    __shared__ float xs[TILE_ROWS][DH];
    __shared__ float Wc_s[DH * RANK];
    __shared__ float A_s[RANK * KMAX];
    __shared__ float V_s[RANK * DH];
    __shared__ float base_s[KMAX * DH];

    const int tid  = threadIdx.x;
    const int lane = tid & 31;
    const int warp = tid >> 5;

    const int chunk = blockIdx.x;
    const int h     = blockIdx.y;
    const int b     = blockIdx.z;
    const int start = chunk * TOK_PER_BLK;

    const int KH   = (h < 2) ? 3 : (h < 4) ? 7 : (h < 6) ? 11 : 21;
    const int padH = KH >> 1;

    const float* xp_base = xproj + ((size_t)b * NTOK) * DMODEL + h * DH;
    for (int idx = tid; idx < TILE_ROWS * DH; idx += 256) {
        int row = idx >> 7;
        int col = idx & 127;
        int gn  = start - PADMAX + row;
        float v = 0.0f;
        if (gn >= 0 && gn < NTOK)
            v = xp_base[(size_t)gn * DMODEL + col];
        xs[row][col] = v;
    }
    for (int idx = tid; idx < DH * RANK; idx += 256)
        Wc_s[idx] = Wc[(size_t)h * DH * RANK + idx];
    for (int idx = tid; idx < RANK * KMAX; idx += 256)
        A_s[idx] = A[(size_t)h * RANK * KMAX + idx];
    for (int idx = tid; idx < RANK * DH; idx += 256)
        V_s[idx] = V[(size_t)h * RANK * DH + idx];
    for (int idx = tid; idx < KMAX * DH; idx += 256)
        base_s[idx] = base[(size_t)h * KMAX * DH + idx];
    __syncthreads();

    const float alpha = 1.0f / (1.0f + __expf(-alphas[h]));
    const float oma   = 1.0f - alpha;

    for (int it = 0; it < TOK_PER_BLK / 8; it++) {
        const int lt     = warp + 8 * it;
        const int center = lt + PADMAX;

        float xv[4];
#pragma unroll
        for (int i = 0; i < 4; i++)
            xv[i] = xs[center][lane + 32 * i];

        float c0 = 0.f, c1 = 0.f, c2 = 0.f, c3 = 0.f;
#pragma unroll
        for (int i = 0; i < 4; i++) {
            int d = lane + 32 * i;
            float x = xv[i];
            c0 = fmaf(x, Wc_s[d * RANK + 0], c0);
            c1 = fmaf(x, Wc_s[d * RANK + 1], c1);
            c2 = fmaf(x, Wc_s[d * RANK + 2], c2);
            c3 = fmaf(x, Wc_s[d * RANK + 3], c3);
        }
#pragma unroll
        for (int off = 16; off > 0; off >>= 1) {
            c0 += __shfl_xor_sync(0xffffffffu, c0, off);
            c1 += __shfl_xor_sync(0xffffffffu, c1, off);
            c2 += __shfl_xor_sync(0xffffffffu, c2, off);
            c3 += __shfl_xor_sync(0xffffffffu, c3, off);
        }

        float acc[4] = {0.f, 0.f, 0.f, 0.f};
        for (int k = 0; k < KH; k++) {
            const float ca0 = c0 * A_s[0 * KMAX + k];
            const float ca1 = c1 * A_s[1 * KMAX + k];
            const float ca2 = c2 * A_s[2 * KMAX + k];
            const float ca3 = c3 * A_s[3 * KMAX + k];
            const int row = center - padH + k;
#pragma unroll
            for (int i = 0; i < 4; i++) {
                int d = lane + 32 * i;
                float dyn = ca0 * V_s[0 * DH + d]
                          + ca1 * V_s[1 * DH + d]
                          + ca2 * V_s[2 * DH + d]
                          + ca3 * V_s[3 * DH + d];
                float kh = alpha * dyn + oma * base_s[k * DH + d];
                acc[i] = fmaf(kh, xs[row][d], acc[i]);
            }
        }

        const int n = start + lt;
        const size_t ob = ((size_t)b * NTOK + n) * DMODEL + h * DH;
#pragma unroll
        for (int i = 0; i < 4; i++) {
            float a = acc[i];
            __nv_bfloat16 hbf = __float2bfloat16(a);
            float hf = __bfloat162float(hbf);
            chi[ob + lane + 32 * i] = hbf;
            clo[ob + lane + 32 * i] = __float2bfloat16(a - hf);
        }
    }
}

// ---------------------------------------------------------------------------
// Launch
// ---------------------------------------------------------------------------
extern "C" void kernel_launch(void* const* d_in, const int* in_sizes, int n_in,
                              void* d_out, int out_size)
{
    const float* x      = (const float*)d_in[0];
    const float* W_in   = (const float*)d_in[1];
    const float* b_in   = (const float*)d_in[2];
    const float* W_out  = (const float*)d_in[3];
    const float* b_out  = (const float*)d_in[4];
    const float* Wc     = (const float*)d_in[5];
    const float* A      = (const float*)d_in[6];
    const float* V      = (const float*)d_in[7];
    const float* base   = (const float*)d_in[8];
    const float* alphas = (const float*)d_in[9];
    float* out = (float*)d_out;

    float* xproj; cudaGetSymbolAddress((void**)&xproj, g_xproj);
    __nv_bfloat16 *xhi, *xlo, *chi, *clo, *wih, *wil, *woh, *wol;
    cudaGetSymbolAddress((void**)&xhi, g_xhi);
    cudaGetSymbolAddress((void**)&xlo, g_xlo);
    cudaGetSymbolAddress((void**)&chi, g_chi);
    cudaGetSymbolAddress((void**)&clo, g_clo);
    cudaGetSymbolAddress((void**)&wih, g_wih);
    cudaGetSymbolAddress((void**)&wil, g_wil);
    cudaGetSymbolAddress((void**)&woh, g_woh);
    cudaGetSymbolAddress((void**)&wol, g_wol);

    cudaFuncSetAttribute(gemm_mma, cudaFuncAttributeMaxDynamicSharedMemorySize, GSMEM);

    // Splits
    {
        int n4x = GM * GK / 4;          // 2,097,152
        split_bf16<<<(n4x + 255) / 256, 256>>>((const float4*)x,
            (uint2*)xhi, (uint2*)xlo, n4x);
        int n4w = GN * GK / 4;          // 262,144
        split_bf16<<<(n4w + 255) / 256, 256>>>((const float4*)W_in,
            (uint2*)wih, (uint2*)wil, n4w);
        split_bf16<<<(n4w + 255) / 256, 256>>>((const float4*)W_out,
            (uint2*)woh, (uint2*)wol, n4w);
    }
    // GEMM1: xproj = x @ W_in^T + b_in
    {
        dim3 grid(GN / 128, GM / 128);   // (8, 64)
        gemm_mma<<<grid, 256, GSMEM>>>(xhi, xlo, wih, wil, b_in, xproj);
    }
    // Per-head dynamic conv -> concat (bf16 hi/lo)
    {
        dim3 grid(NTOK / TOK_PER_BLK, NHEADS, Bsz);
        dka_conv_kernel<<<grid, 256>>>(xproj, Wc, A, V, base, alphas, chi, clo);
    }
    // GEMM2: out = concat @ W_out^T + b_out
    {
        dim3 grid(GN / 128, GM / 128);
        gemm_mma<<<grid, 256, GSMEM>>>(chi, clo, woh, wol, b_out, out);
    }
}

// round 11
// speedup vs baseline: 4.6699x; 1.9300x over previous
#include <cuda_runtime.h>
#include <cuda_fp16.h>
#include <cstdint>
#include <math.h>

// Problem constants
#define Bsz 2
#define NTOK 4096
#define DMODEL 1024
#define NHEADS 8
#define DH 128
#define RANK 4
#define KMAX 21
#define PADMAX 10   // KMAX/2

#define GM (Bsz * NTOK)   // 8192
#define GK DMODEL         // 1024
#define GN DMODEL         // 1024

// Scratch (device globals; runtime allocation is forbidden)
__device__ float g_xproj[GM * GK];     // x @ W_in.T + b_in (fp32 for conv)
__device__ __half g_xh[GM * GK];       // fp16 copy of x
__device__ __half g_ch[GM * GK];       // fp16 concat (written by conv)
__device__ __half g_wi[GN * GK];       // fp16 W_in
__device__ __half g_wo[GN * GK];       // fp16 W_out

// ===========================================================================
// Elementwise fp32 -> fp16 convert.  n4 = element count / 4.
// ===========================================================================
__global__ __launch_bounds__(256)
void cvt_f16(const float4* __restrict__ in, uint2* __restrict__ out, int n4)
{
    int i = blockIdx.x * 256 + threadIdx.x;
    if (i >= n4) return;
    float4 v = in[i];
    __half2 h01 = __floats2half2_rn(v.x, v.y);
    __half2 h23 = __floats2half2_rn(v.z, v.w);
    uint2 u;
    u.x = *reinterpret_cast<const uint32_t*>(&h01);
    u.y = *reinterpret_cast<const uint32_t*>(&h23);
    out[i] = u;
}

// ===========================================================================
// mma.sync GEMM:  C[M,N] = A[M,K] @ W[N,K]^T + bias[N]   (fp32 out)
// A, W given as fp16.  Single MMA per fragment pair, fp32 accumulators.
// CTA tile 128x128, 8 warps (warp tile 32x64), K-chunk 64, THREE-stage
// cp.async pipeline, one __syncthreads per chunk, TWO CTAs PER SM
// (launch_bounds(256,2); smem 2x110592 = 216KiB of 228KiB).
// Smem rows padded to 144B (128B payload): row stride mod 32 banks = 4
// -> 8 consecutive ldmatrix rows hit distinct banks.
// ===========================================================================
#define CH_K 64
#define NCHUNK (GK / CH_K)     // 16
#define NSTAGE 3
#define ROWB 144               // bytes per smem row (64 fp16 + 16B pad)
#define TSZ (128 * ROWB)       // 18432 bytes per tensor tile
#define STG (2 * TSZ)          // 36864 bytes per stage (A, B)
#define GSMEM (NSTAGE * STG)   // 110592 bytes

__device__ __forceinline__ uint32_t smem_u32(const void* p) {
    uint32_t a;
    asm("{ .reg .u64 t; cvta.to.shared.u64 t, %1; cvt.u32.u64 %0, t; }"
        : "=r"(a) : "l"(p));
    return a;
}

#define LDMX4(r, addr) \
    asm volatile("ldmatrix.sync.aligned.m8n8.x4.shared.b16 {%0,%1,%2,%3}, [%4];" \
        : "=r"((r)[0]), "=r"((r)[1]), "=r"((r)[2]), "=r"((r)[3]) : "r"(addr))

#define MMAF16(c, a, b0, b1) \
    asm volatile("mma.sync.aligned.m16n8k16.row.col.f32.f16.f16.f32 " \
        "{%0,%1,%2,%3}, {%4,%5,%6,%7}, {%8,%9}, {%0,%1,%2,%3};" \
        : "+f"((c)[0]), "+f"((c)[1]), "+f"((c)[2]), "+f"((c)[3]) \
        : "r"((a)[0]), "r"((a)[1]), "r"((a)[2]), "r"((a)[3]), "r"(b0), "r"(b1))

__global__ __launch_bounds__(256, 2)
void gemm_mma(const __half* __restrict__ Ah,
              const __half* __restrict__ Bh,
              const float* __restrict__ bias,
              float* __restrict__ C)
{
    extern __shared__ __align__(128) char smem[];
    const uint32_t sb = smem_u32(smem);
    const int tid = threadIdx.x;
    const int lane = tid & 31;
    const int wid = tid >> 5;
    const int warp_m = wid & 3;        // 4 warps along M (32 rows each)
    const int warp_n = wid >> 2;       // 2 warps along N (64 cols each)
    const int row0 = blockIdx.y * 128;
    const int col0 = blockIdx.x * 128;

    const __half* gsrc[2];
    gsrc[0] = Ah + (size_t)row0 * GK;
    gsrc[1] = Bh + (size_t)col0 * GK;

    float acc[2][8][4];
#pragma unroll
    for (int mt = 0; mt < 2; mt++)
#pragma unroll
        for (int nt = 0; nt < 8; nt++)
#pragma unroll
            for (int j = 0; j < 4; j++)
                acc[mt][nt][j] = 0.0f;

    // Per stage: 2 tensors x 128 rows x 8 chunks(16B) = 2048 chunks;
    // 256 threads -> 8 chunks each (4 per tensor).
#define ISSUE_STAGE(CH)                                                       \
    do {                                                                      \
        const int _k0 = (CH) * CH_K;                                          \
        const uint32_t _sbase = sb + ((CH) % NSTAGE) * STG;                   \
        _Pragma("unroll")                                                     \
        for (int _t = 0; _t < 2; _t++) {                                      \
            _Pragma("unroll")                                                 \
            for (int _j = 0; _j < 4; _j++) {                                  \
                int _idx = tid + _j * 256;     /* 0..1023 */                  \
                int _r = _idx >> 3;            /* 0..127 */                   \
                int _c = _idx & 7;             /* 16B chunk in row */         \
                const __half* _g = gsrc[_t] + (size_t)_r * GK + _k0 + _c * 8; \
                uint32_t _s = _sbase + _t * TSZ + _r * ROWB + _c * 16;        \
                asm volatile("cp.async.cg.shared.global [%0], [%1], 16;"      \
                             :: "r"(_s), "l"(_g));                            \
            }                                                                 \
        }                                                                     \
        asm volatile("cp.async.commit_group;");                               \
    } while (0)

    // Prologue: fill 2 of the 3 stages.
    ISSUE_STAGE(0);
    ISSUE_STAGE(1);

    for (int ch = 0; ch < NCHUNK; ch++) {
        // Group ch complete (<=1 newer pending).
        asm volatile("cp.async.wait_group 1;");
        __syncthreads();   // stage ch visible; all warps done computing ch-1.

        // Prefetch ch+2 into buffer (ch+2)%3 == (ch-1)%3 — safe per barrier.
        // Issued BEFORE compute so the loads overlap this chunk's MMAs.
        // Committed every iteration (empty in tail) so wait count is uniform.
        if (ch + 2 < NCHUNK) {
            ISSUE_STAGE(ch + 2);
        } else {
            asm volatile("cp.async.commit_group;");
        }

        const uint32_t stBase = sb + (ch % NSTAGE) * STG;
#pragma unroll
        for (int ks = 0; ks < 4; ks++) {
            // --- A fragments: rows warp_m*32, two m16 tiles ---
            uint32_t a[2][4];
            {
                const uint32_t kb = (ks * 16 + (lane >> 4) * 8) * 2;
#pragma unroll
                for (int mt = 0; mt < 2; mt++) {
                    uint32_t ad = stBase
                                + (warp_m * 32 + mt * 16 + (lane & 15)) * ROWB + kb;
                    LDMX4(a[mt], ad);
                }
            }
            // --- B fragments per n16 tile; immediately consumed ---
#pragma unroll
            for (int pr = 0; pr < 4; pr++) {
                const uint32_t bd = stBase + TSZ
                    + (warp_n * 64 + pr * 16 + ((lane >> 4) & 1) * 8 + (lane & 7)) * ROWB
                    + (ks * 16 + ((lane >> 3) & 1) * 8) * 2;
                uint32_t b[4];
                LDMX4(b, bd);
#pragma unroll
                for (int mt = 0; mt < 2; mt++) {
                    MMAF16(acc[mt][2 * pr],     a[mt], b[0], b[1]);
                    MMAF16(acc[mt][2 * pr + 1], a[mt], b[2], b[3]);
                }
            }
        }
    }
#undef ISSUE_STAGE

    // Epilogue: mma c-fragment layout -> C with bias
#pragma unroll
    for (int mt = 0; mt < 2; mt++) {
        const int r = row0 + warp_m * 32 + mt * 16 + (lane >> 2);
#pragma unroll
        for (int nt = 0; nt < 8; nt++) {
            const int cc = col0 + warp_n * 64 + nt * 8 + (lane & 3) * 2;
            const float b0 = bias[cc], b1 = bias[cc + 1];
            float2 v0, v1;
            v0.x = acc[mt][nt][0] + b0;  v0.y = acc[mt][nt][1] + b1;
            v1.x = acc[mt][nt][2] + b0;  v1.y = acc[mt][nt][3] + b1;
            *(float2*)(C + (size_t)r * GN + cc) = v0;
            *(float2*)(C + (size_t)(r + 8) * GN + cc) = v1;
        }
    }
}

// ---------------------------------------------------------------------------
// Per-head dynamic-kernel conv; epilogue emits fp16 directly.
// ---------------------------------------------------------------------------
#define TOK_PER_BLK 32
#define TILE_ROWS (TOK_PER_BLK + 2 * PADMAX)   // 52

__global__ __launch_bounds__(256, 4)
void dka_conv_kernel(const float* __restrict__ xproj,
                     const float* __restrict__ Wc,
                     const float* __restrict__ A,
                     const float* __restrict__ V,
                     const float* __restrict__ base,
                     const float* __restrict__ alphas,
                     __half* __restrict__ chd)
{
    __shared__ float xs[TILE_ROWS][DH];
    __shared__ float Wc_s[DH * RANK];
    __shared__ float A_s[RANK * KMAX];
    __shared__ float V_s[RANK * DH];
    __shared__ float base_s[KMAX * DH];

    const int tid  = threadIdx.x;
    const int lane = tid & 31;
    const int warp = tid >> 5;

    const int chunk = blockIdx.x;
    const int h     = blockIdx.y;
    const int b     = blockIdx.z;
    const int start = chunk * TOK_PER_BLK;

    const int KH   = (h < 2) ? 3 : (h < 4) ? 7 : (h < 6) ? 11 : 21;
    const int padH = KH >> 1;

    const float* xp_base = xproj + ((size_t)b * NTOK) * DMODEL + h * DH;
    for (int idx = tid; idx < TILE_ROWS * DH; idx += 256) {
        int row = idx >> 7;
        int col = idx & 127;
        int gn  = start - PADMAX + row;
        float v = 0.0f;
        if (gn >= 0 && gn < NTOK)
            v = xp_base[(size_t)gn * DMODEL + col];
        xs[row][col] = v;
    }
    for (int idx = tid; idx < DH * RANK; idx += 256)
        Wc_s[idx] = Wc[(size_t)h * DH * RANK + idx];
    for (int idx = tid; idx < RANK * KMAX; idx += 256)
        A_s[idx] = A[(size_t)h * RANK * KMAX + idx];
    for (int idx = tid; idx < RANK * DH; idx += 256)
        V_s[idx] = V[(size_t)h * RANK * DH + idx];
    for (int idx = tid; idx < KMAX * DH; idx += 256)
        base_s[idx] = base[(size_t)h * KMAX * DH + idx];
    __syncthreads();

    const float alpha = 1.0f / (1.0f + __expf(-alphas[h]));
    const float oma   = 1.0f - alpha;

    for (int it = 0; it < TOK_PER_BLK / 8; it++) {
        const int lt     = warp + 8 * it;
        const int center = lt + PADMAX;

        float xv[4];
#pragma unroll
        for (int i = 0; i < 4; i++)
            xv[i] = xs[center][lane + 32 * i];

        float c0 = 0.f, c1 = 0.f, c2 = 0.f, c3 = 0.f;
#pragma unroll
        for (int i = 0; i < 4; i++) {
            int d = lane + 32 * i;
            float x = xv[i];
            c0 = fmaf(x, Wc_s[d * RANK + 0], c0);
            c1 = fmaf(x, Wc_s[d * RANK + 1], c1);
            c2 = fmaf(x, Wc_s[d * RANK + 2], c2);
            c3 = fmaf(x, Wc_s[d * RANK + 3], c3);
        }
#pragma unroll
        for (int off = 16; off > 0; off >>= 1) {
            c0 += __shfl_xor_sync(0xffffffffu, c0, off);
            c1 += __shfl_xor_sync(0xffffffffu, c1, off);
            c2 += __shfl_xor_sync(0xffffffffu, c2, off);
            c3 += __shfl_xor_sync(0xffffffffu, c3, off);
        }

        float acc[4] = {0.f, 0.f, 0.f, 0.f};
        for (int k = 0; k < KH; k++) {
            const float ca0 = c0 * A_s[0 * KMAX + k];
            const float ca1 = c1 * A_s[1 * KMAX + k];
            const float ca2 = c2 * A_s[2 * KMAX + k];
            const float ca3 = c3 * A_s[3 * KMAX + k];
            const int row = center - padH + k;
#pragma unroll
            for (int i = 0; i < 4; i++) {
                int d = lane + 32 * i;
                float dyn = ca0 * V_s[0 * DH + d]
                          + ca1 * V_s[1 * DH + d]
                          + ca2 * V_s[2 * DH + d]
                          + ca3 * V_s[3 * DH + d];
                float kh = alpha * dyn + oma * base_s[k * DH + d];
                acc[i] = fmaf(kh, xs[row][d], acc[i]);
            }
        }

        const int n = start + lt;
        const size_t ob = ((size_t)b * NTOK + n) * DMODEL + h * DH;
#pragma unroll
        for (int i = 0; i < 4; i++)
            chd[ob + lane + 32 * i] = __float2half_rn(acc[i]);
    }
}

// ---------------------------------------------------------------------------
// Launch
// ---------------------------------------------------------------------------
extern "C" void kernel_launch(void* const* d_in, const int* in_sizes, int n_in,
                              void* d_out, int out_size)
{
    const float* x      = (const float*)d_in[0];
    const float* W_in   = (const float*)d_in[1];
    const float* b_in   = (const float*)d_in[2];
    const float* W_out  = (const float*)d_in[3];
    const float* b_out  = (const float*)d_in[4];
    const float* Wc     = (const float*)d_in[5];
    const float* A      = (const float*)d_in[6];
    const float* V      = (const float*)d_in[7];
    const float* base   = (const float*)d_in[8];
    const float* alphas = (const float*)d_in[9];
    float* out = (float*)d_out;

    float* xproj; cudaGetSymbolAddress((void**)&xproj, g_xproj);
    __half *xh, *ch, *wi, *wo;
    cudaGetSymbolAddress((void**)&xh, g_xh);
    cudaGetSymbolAddress((void**)&ch, g_ch);
    cudaGetSymbolAddress((void**)&wi, g_wi);
    cudaGetSymbolAddress((void**)&wo, g_wo);

    cudaFuncSetAttribute(gemm_mma, cudaFuncAttributeMaxDynamicSharedMemorySize, GSMEM);

    // fp16 converts
    {
        int n4x = GM * GK / 4;          // 2,097,152
        cvt_f16<<<(n4x + 255) / 256, 256>>>((const float4*)x, (uint2*)xh, n4x);
        int n4w = GN * GK / 4;          // 262,144
        cvt_f16<<<(n4w + 255) / 256, 256>>>((const float4*)W_in,  (uint2*)wi, n4w);
        cvt_f16<<<(n4w + 255) / 256, 256>>>((const float4*)W_out, (uint2*)wo, n4w);
    }
    // GEMM1: xproj = x @ W_in^T + b_in
    {
        dim3 grid(GN / 128, GM / 128);   // (8, 64)
        gemm_mma<<<grid, 256, GSMEM>>>(xh, wi, b_in, xproj);
    }
    // Per-head dynamic conv -> concat (fp16)
    {
        dim3 grid(NTOK / TOK_PER_BLK, NHEADS, Bsz);
        dka_conv_kernel<<<grid, 256>>>(xproj, Wc, A, V, base, alphas, ch);
    }
    // GEMM2: out = concat @ W_out^T + b_out
    {
        dim3 grid(GN / 128, GM / 128);
        gemm_mma<<<grid, 256, GSMEM>>>(ch, wo, b_out, out);
    }
}

// round 12
// speedup vs baseline: 4.7059x; 1.0077x over previous
#include <cuda_runtime.h>
#include <cuda_fp16.h>
#include <cstdint>
#include <math.h>

// Problem constants
#define Bsz 2
#define NTOK 4096
#define DMODEL 1024
#define NHEADS 8
#define DH 128
#define RANK 4
#define KMAX 21
#define PADMAX 10   // KMAX/2

#define GM (Bsz * NTOK)   // 8192
#define GK DMODEL         // 1024
#define GN DMODEL         // 1024

// Scratch (device globals; runtime allocation is forbidden)
__device__ __half g_xp16[GM * GK];     // xproj fp16 (GEMM1 out, conv in)
__device__ __half g_xh[GM * GK];       // fp16 copy of x
__device__ __half g_ch[GM * GK];       // fp16 concat (written by conv)
__device__ __half g_wi[GN * GK];       // fp16 W_in
__device__ __half g_wo[GN * GK];       // fp16 W_out

// ===========================================================================
// Elementwise fp32 -> fp16 convert.  n4 = element count / 4.
// ===========================================================================
__global__ __launch_bounds__(256)
void cvt_f16(const float4* __restrict__ in, uint2* __restrict__ out, int n4)
{
    int i = blockIdx.x * 256 + threadIdx.x;
    if (i >= n4) return;
    float4 v = in[i];
    __half2 h01 = __floats2half2_rn(v.x, v.y);
    __half2 h23 = __floats2half2_rn(v.z, v.w);
    uint2 u;
    u.x = *reinterpret_cast<const uint32_t*>(&h01);
    u.y = *reinterpret_cast<const uint32_t*>(&h23);
    out[i] = u;
}

// ===========================================================================
// mma.sync GEMM:  C[M,N] = A[M,K] @ W[N,K]^T + bias[N]
// OUT_HALF=1 -> fp16 output, else fp32.  fp16 inputs, fp32 accum.
// CTA tile 128x128, 8 warps (warp tile 32x64), K-chunk 64, THREE-stage
// cp.async pipeline, one __syncthreads per chunk, TWO CTAs PER SM.
// ===========================================================================
#define CH_K 64
#define NCHUNK (GK / CH_K)     // 16
#define NSTAGE 3
#define ROWB 144               // bytes per smem row (64 fp16 + 16B pad)
#define TSZ (128 * ROWB)       // 18432 bytes per tensor tile
#define STG (2 * TSZ)          // 36864 bytes per stage (A, B)
#define GSMEM (NSTAGE * STG)   // 110592 bytes

__device__ __forceinline__ uint32_t smem_u32(const void* p) {
    uint32_t a;
    asm("{ .reg .u64 t; cvta.to.shared.u64 t, %1; cvt.u32.u64 %0, t; }"
        : "=r"(a) : "l"(p));
    return a;
}

#define LDMX4(r, addr) \
    asm volatile("ldmatrix.sync.aligned.m8n8.x4.shared.b16 {%0,%1,%2,%3}, [%4];" \
        : "=r"((r)[0]), "=r"((r)[1]), "=r"((r)[2]), "=r"((r)[3]) : "r"(addr))

#define MMAF16(c, a, b0, b1) \
    asm volatile("mma.sync.aligned.m16n8k16.row.col.f32.f16.f16.f32 " \
        "{%0,%1,%2,%3}, {%4,%5,%6,%7}, {%8,%9}, {%0,%1,%2,%3};" \
        : "+f"((c)[0]), "+f"((c)[1]), "+f"((c)[2]), "+f"((c)[3]) \
        : "r"((a)[0]), "r"((a)[1]), "r"((a)[2]), "r"((a)[3]), "r"(b0), "r"(b1))

template <int OUT_HALF>
__global__ __launch_bounds__(256, 2)
void gemm_mma(const __half* __restrict__ Ah,
              const __half* __restrict__ Bh,
              const float* __restrict__ bias,
              void* __restrict__ Cout)
{
    extern __shared__ __align__(128) char smem[];
    const uint32_t sb = smem_u32(smem);
    const int tid = threadIdx.x;
    const int lane = tid & 31;
    const int wid = tid >> 5;
    const int warp_m = wid & 3;        // 4 warps along M (32 rows each)
    const int warp_n = wid >> 2;       // 2 warps along N (64 cols each)
    const int row0 = blockIdx.y * 128;
    const int col0 = blockIdx.x * 128;

    const __half* gsrc[2];
    gsrc[0] = Ah + (size_t)row0 * GK;
    gsrc[1] = Bh + (size_t)col0 * GK;

    float acc[2][8][4];
#pragma unroll
    for (int mt = 0; mt < 2; mt++)
#pragma unroll
        for (int nt = 0; nt < 8; nt++)
#pragma unroll
            for (int j = 0; j < 4; j++)
                acc[mt][nt][j] = 0.0f;

#define ISSUE_STAGE(CH)                                                       \
    do {                                                                      \
        const int _k0 = (CH) * CH_K;                                          \
        const uint32_t _sbase = sb + ((CH) % NSTAGE) * STG;                   \
        _Pragma("unroll")                                                     \
        for (int _t = 0; _t < 2; _t++) {                                      \
            _Pragma("unroll")                                                 \
            for (int _j = 0; _j < 4; _j++) {                                  \
                int _idx = tid + _j * 256;     /* 0..1023 */                  \
                int _r = _idx >> 3;            /* 0..127 */                   \
                int _c = _idx & 7;             /* 16B chunk in row */         \
                const __half* _g = gsrc[_t] + (size_t)_r * GK + _k0 + _c * 8; \
                uint32_t _s = _sbase + _t * TSZ + _r * ROWB + _c * 16;        \
                asm volatile("cp.async.cg.shared.global [%0], [%1], 16;"      \
                             :: "r"(_s), "l"(_g));                            \
            }                                                                 \
        }                                                                     \
        asm volatile("cp.async.commit_group;");                               \
    } while (0)

    ISSUE_STAGE(0);
    ISSUE_STAGE(1);

    for (int ch = 0; ch < NCHUNK; ch++) {
        asm volatile("cp.async.wait_group 1;");
        __syncthreads();

        if (ch + 2 < NCHUNK) {
            ISSUE_STAGE(ch + 2);
        } else {
            asm volatile("cp.async.commit_group;");
        }

        const uint32_t stBase = sb + (ch % NSTAGE) * STG;
#pragma unroll
        for (int ks = 0; ks < 4; ks++) {
            uint32_t a[2][4];
            {
                const uint32_t kb = (ks * 16 + (lane >> 4) * 8) * 2;
#pragma unroll
                for (int mt = 0; mt < 2; mt++) {
                    uint32_t ad = stBase
                                + (warp_m * 32 + mt * 16 + (lane & 15)) * ROWB + kb;
                    LDMX4(a[mt], ad);
                }
            }
#pragma unroll
            for (int pr = 0; pr < 4; pr++) {
                const uint32_t bd = stBase + TSZ
                    + (warp_n * 64 + pr * 16 + ((lane >> 4) & 1) * 8 + (lane & 7)) * ROWB
                    + (ks * 16 + ((lane >> 3) & 1) * 8) * 2;
                uint32_t b[4];
                LDMX4(b, bd);
#pragma unroll
                for (int mt = 0; mt < 2; mt++) {
                    MMAF16(acc[mt][2 * pr],     a[mt], b[0], b[1]);
                    MMAF16(acc[mt][2 * pr + 1], a[mt], b[2], b[3]);
                }
            }
        }
    }
#undef ISSUE_STAGE

    // Epilogue
#pragma unroll
    for (int mt = 0; mt < 2; mt++) {
        const int r = row0 + warp_m * 32 + mt * 16 + (lane >> 2);
#pragma unroll
        for (int nt = 0; nt < 8; nt++) {
            const int cc = col0 + warp_n * 64 + nt * 8 + (lane & 3) * 2;
            const float b0 = bias[cc], b1 = bias[cc + 1];
            float v00 = acc[mt][nt][0] + b0, v01 = acc[mt][nt][1] + b1;
            float v10 = acc[mt][nt][2] + b0, v11 = acc[mt][nt][3] + b1;
            if (OUT_HALF) {
                __half* C = (__half*)Cout;
                __half2 h0 = __floats2half2_rn(v00, v01);
                __half2 h1 = __floats2half2_rn(v10, v11);
                *(__half2*)(C + (size_t)r * GN + cc) = h0;
                *(__half2*)(C + (size_t)(r + 8) * GN + cc) = h1;
            } else {
                float* C = (float*)Cout;
                float2 v0, v1;
                v0.x = v00; v0.y = v01;
                v1.x = v10; v1.y = v11;
                *(float2*)(C + (size_t)r * GN + cc) = v0;
                *(float2*)(C + (size_t)(r + 8) * GN + cc) = v1;
            }
        }
    }
}

// ---------------------------------------------------------------------------
// Per-head dynamic-kernel conv; fp16 input (xproj), fp16 output (concat).
// 64 tokens per block, fp32 compute in smem.
// ---------------------------------------------------------------------------
#define TOK_PER_BLK 64
#define TILE_ROWS (TOK_PER_BLK + 2 * PADMAX)   // 84
// dynamic smem floats: xs 84*128=10752, Wc 512, A 84, V 512, base 2688
#define CONV_SMEM ((TILE_ROWS * DH + DH * RANK + RANK * KMAX + RANK * DH + KMAX * DH) * 4)

__global__ __launch_bounds__(256)
void dka_conv_kernel(const __half* __restrict__ xp,
                     const float* __restrict__ Wc,
                     const float* __restrict__ A,
                     const float* __restrict__ V,
                     const float* __restrict__ base,
                     const float* __restrict__ alphas,
                     __half* __restrict__ chd)
{
    extern __shared__ __align__(16) char cms[];
    float* xs     = (float*)cms;                    // [TILE_ROWS][DH]
    float* Wc_s   = xs + TILE_ROWS * DH;            // [DH*RANK]
    float* A_s    = Wc_s + DH * RANK;               // [RANK*KMAX]
    float* V_s    = A_s + RANK * KMAX;              // [RANK*DH]
    float* base_s = V_s + RANK * DH;                // [KMAX*DH]

    const int tid  = threadIdx.x;
    const int lane = tid & 31;
    const int warp = tid >> 5;

    const int chunk = blockIdx.x;
    const int h     = blockIdx.y;
    const int b     = blockIdx.z;
    const int start = chunk * TOK_PER_BLK;

    const int KH   = (h < 2) ? 3 : (h < 4) ? 7 : (h < 6) ? 11 : 21;
    const int padH = KH >> 1;

    // --- load x tile (fp16 -> fp32), vectorized 8 halves per thread-iter ---
    const __half* xp_base = xp + ((size_t)b * NTOK) * DMODEL + h * DH;
    for (int idx = tid; idx < TILE_ROWS * (DH / 8); idx += 256) {
        int row = idx >> 4;           // /16 chunks per row
        int c8  = (idx & 15) * 8;
        int gn  = start - PADMAX + row;
        float* dst = xs + row * DH + c8;
        if (gn >= 0 && gn < NTOK) {
            uint4 raw = *(const uint4*)(xp_base + (size_t)gn * DMODEL + c8);
            const __half2* hp = (const __half2*)&raw;
#pragma unroll
            for (int j = 0; j < 4; j++) {
                float2 f = __half22float2(hp[j]);
                dst[2 * j]     = f.x;
                dst[2 * j + 1] = f.y;
            }
        } else {
#pragma unroll
            for (int j = 0; j < 8; j++) dst[j] = 0.0f;
        }
    }
    for (int idx = tid; idx < DH * RANK; idx += 256)
        Wc_s[idx] = Wc[(size_t)h * DH * RANK + idx];
    for (int idx = tid; idx < RANK * KMAX; idx += 256)
        A_s[idx] = A[(size_t)h * RANK * KMAX + idx];
    for (int idx = tid; idx < RANK * DH; idx += 256)
        V_s[idx] = V[(size_t)h * RANK * DH + idx];
    for (int idx = tid; idx < KMAX * DH; idx += 256)
        base_s[idx] = base[(size_t)h * KMAX * DH + idx];
    __syncthreads();

    const float alpha = 1.0f / (1.0f + __expf(-alphas[h]));
    const float oma   = 1.0f - alpha;

    for (int it = 0; it < TOK_PER_BLK / 8; it++) {
        const int lt     = warp + 8 * it;
        const int center = lt + PADMAX;

        float xv[4];
#pragma unroll
        for (int i = 0; i < 4; i++)
            xv[i] = xs[center * DH + lane + 32 * i];

        float c0 = 0.f, c1 = 0.f, c2 = 0.f, c3 = 0.f;
#pragma unroll
        for (int i = 0; i < 4; i++) {
            int d = lane + 32 * i;
            float x = xv[i];
            c0 = fmaf(x, Wc_s[d * RANK + 0], c0);
            c1 = fmaf(x, Wc_s[d * RANK + 1], c1);
            c2 = fmaf(x, Wc_s[d * RANK + 2], c2);
            c3 = fmaf(x, Wc_s[d * RANK + 3], c3);
        }
#pragma unroll
        for (int off = 16; off > 0; off >>= 1) {
            c0 += __shfl_xor_sync(0xffffffffu, c0, off);
            c1 += __shfl_xor_sync(0xffffffffu, c1, off);
            c2 += __shfl_xor_sync(0xffffffffu, c2, off);
            c3 += __shfl_xor_sync(0xffffffffu, c3, off);
        }

        float acc[4] = {0.f, 0.f, 0.f, 0.f};
        for (int k = 0; k < KH; k++) {
            const float ca0 = c0 * A_s[0 * KMAX + k];
            const float ca1 = c1 * A_s[1 * KMAX + k];
            const float ca2 = c2 * A_s[2 * KMAX + k];
            const float ca3 = c3 * A_s[3 * KMAX + k];
            const float* xr = xs + (center - padH + k) * DH;
#pragma unroll
            for (int i = 0; i < 4; i++) {
                int d = lane + 32 * i;
                float dyn = ca0 * V_s[0 * DH + d]
                          + ca1 * V_s[1 * DH + d]
                          + ca2 * V_s[2 * DH + d]
                          + ca3 * V_s[3 * DH + d];
                float kh = alpha * dyn + oma * base_s[k * DH + d];
                acc[i] = fmaf(kh, xr[d], acc[i]);
            }
        }

        const int n = start + lt;
        const size_t ob = ((size_t)b * NTOK + n) * DMODEL + h * DH;
#pragma unroll
        for (int i = 0; i < 4; i++)
            chd[ob + lane + 32 * i] = __float2half_rn(acc[i]);
    }
}

// ---------------------------------------------------------------------------
// Launch
// ---------------------------------------------------------------------------
extern "C" void kernel_launch(void* const* d_in, const int* in_sizes, int n_in,
                              void* d_out, int out_size)
{
    const float* x      = (const float*)d_in[0];
    const float* W_in   = (const float*)d_in[1];
    const float* b_in   = (const float*)d_in[2];
    const float* W_out  = (const float*)d_in[3];
    const float* b_out  = (const float*)d_in[4];
    const float* Wc     = (const float*)d_in[5];
    const float* A      = (const float*)d_in[6];
    const float* V      = (const float*)d_in[7];
    const float* base   = (const float*)d_in[8];
    const float* alphas = (const float*)d_in[9];
    float* out = (float*)d_out;

    __half *xp16, *xh, *ch, *wi, *wo;
    cudaGetSymbolAddress((void**)&xp16, g_xp16);
    cudaGetSymbolAddress((void**)&xh, g_xh);
    cudaGetSymbolAddress((void**)&ch, g_ch);
    cudaGetSymbolAddress((void**)&wi, g_wi);
    cudaGetSymbolAddress((void**)&wo, g_wo);

    cudaFuncSetAttribute(gemm_mma<0>, cudaFuncAttributeMaxDynamicSharedMemorySize, GSMEM);
    cudaFuncSetAttribute(gemm_mma<1>, cudaFuncAttributeMaxDynamicSharedMemorySize, GSMEM);
    cudaFuncSetAttribute(dka_conv_kernel, cudaFuncAttributeMaxDynamicSharedMemorySize, CONV_SMEM);

    // fp16 converts
    {
        int n4x = GM * GK / 4;          // 2,097,152
        cvt_f16<<<(n4x + 255) / 256, 256>>>((const float4*)x, (uint2*)xh, n4x);
        int n4w = GN * GK / 4;          // 262,144
        cvt_f16<<<(n4w + 255) / 256, 256>>>((const float4*)W_in,  (uint2*)wi, n4w);
        cvt_f16<<<(n4w + 255) / 256, 256>>>((const float4*)W_out, (uint2*)wo, n4w);
    }
    // GEMM1: xp16 = fp16(x @ W_in^T + b_in)
    {
        dim3 grid(GN / 128, GM / 128);   // (8, 64)
        gemm_mma<1><<<grid, 256, GSMEM>>>(xh, wi, b_in, xp16);
    }
    // Per-head dynamic conv -> concat (fp16)
    {
        dim3 grid(NTOK / TOK_PER_BLK, NHEADS, Bsz);
        dka_conv_kernel<<<grid, 256, CONV_SMEM>>>(xp16, Wc, A, V, base, alphas, ch);
    }
    // GEMM2: out = concat @ W_out^T + b_out   (fp32 out)
    {
        dim3 grid(GN / 128, GM / 128);
        gemm_mma<0><<<grid, 256, GSMEM>>>(ch, wo, b_out, out);
    }
}

// round 13
// speedup vs baseline: 4.9490x; 1.0517x over previous
#include <cuda_runtime.h>
#include <cuda_fp16.h>
#include <cstdint>
#include <math.h>

// Problem constants
#define Bsz 2
#define NTOK 4096
#define DMODEL 1024
#define NHEADS 8
#define DH 128
#define RANK 4
#define KMAX 21
#define PADMAX 10   // KMAX/2

#define GM (Bsz * NTOK)   // 8192
#define GK DMODEL         // 1024
#define GN DMODEL         // 1024

// Scratch (device globals; runtime allocation is forbidden)
__device__ __half g_xp16[GM * GK];     // xproj fp16 (GEMM1 out, conv in)
__device__ __half g_xh[GM * GK];       // fp16 copy of x
__device__ __half g_ch[GM * GK];       // fp16 concat (written by conv)
__device__ __half g_wi[GN * GK];       // fp16 W_in
__device__ __half g_wo[GN * GK];       // fp16 W_out

// ===========================================================================
// Fused fp32 -> fp16 convert of x, W_in, W_out in ONE launch.
// Block ranges: [0, XB) -> x, [XB, XB+WB) -> W_in, [XB+WB, XB+2WB) -> W_out.
// ===========================================================================
#define N4X (GM * GK / 4)     // 2,097,152 float4
#define N4W (GN * GK / 4)     //   262,144 float4
#define XB (N4X / 256)        // 8192 blocks
#define WB (N4W / 256)        // 1024 blocks

__global__ __launch_bounds__(256)
void cvt_all(const float4* __restrict__ x, const float4* __restrict__ wi,
             const float4* __restrict__ wo,
             uint2* __restrict__ xh, uint2* __restrict__ wih,
             uint2* __restrict__ woh)
{
    int blk = blockIdx.x;
    const float4* src;
    uint2* dst;
    int i;
    if (blk < XB)            { src = x;  dst = xh;  i = blk * 256 + threadIdx.x; }
    else if (blk < XB + WB)  { src = wi; dst = wih; i = (blk - XB) * 256 + threadIdx.x; }
    else                     { src = wo; dst = woh; i = (blk - XB - WB) * 256 + threadIdx.x; }
    float4 v = src[i];
    __half2 h01 = __floats2half2_rn(v.x, v.y);
    __half2 h23 = __floats2half2_rn(v.z, v.w);
    uint2 u;
    u.x = *reinterpret_cast<const uint32_t*>(&h01);
    u.y = *reinterpret_cast<const uint32_t*>(&h23);
    dst[i] = u;
}

// ===========================================================================
// mma.sync GEMM:  C[M,N] = A[M,K] @ W[N,K]^T + bias[N]
// OUT_HALF=1 -> fp16 output, else fp32.  fp16 inputs, fp32 accum.
// CTA tile 128x128, 8 warps (warp tile 32x64), K-chunk 64, THREE-stage
// cp.async pipeline, one __syncthreads per chunk, TWO CTAs PER SM.
// Inner loop: ALL fragments (2xA + 4xB LDSM) loaded up front per ks-step,
// then 16 MMAs issued as one block (breaks LDSM->MMA serialization).
// ===========================================================================
#define CH_K 64
#define NCHUNK (GK / CH_K)     // 16
#define NSTAGE 3
#define ROWB 144               // bytes per smem row (64 fp16 + 16B pad)
#define TSZ (128 * ROWB)       // 18432 bytes per tensor tile
#define STG (2 * TSZ)          // 36864 bytes per stage (A, B)
#define GSMEM (NSTAGE * STG)   // 110592 bytes

__device__ __forceinline__ uint32_t smem_u32(const void* p) {
    uint32_t a;
    asm("{ .reg .u64 t; cvta.to.shared.u64 t, %1; cvt.u32.u64 %0, t; }"
        : "=r"(a) : "l"(p));
    return a;
}

#define LDMX4(r, addr) \
    asm volatile("ldmatrix.sync.aligned.m8n8.x4.shared.b16 {%0,%1,%2,%3}, [%4];" \
        : "=r"((r)[0]), "=r"((r)[1]), "=r"((r)[2]), "=r"((r)[3]) : "r"(addr))

#define MMAF16(c, a, b0, b1) \
    asm volatile("mma.sync.aligned.m16n8k16.row.col.f32.f16.f16.f32 " \
        "{%0,%1,%2,%3}, {%4,%5,%6,%7}, {%8,%9}, {%0,%1,%2,%3};" \
        : "+f"((c)[0]), "+f"((c)[1]), "+f"((c)[2]), "+f"((c)[3]) \
        : "r"((a)[0]), "r"((a)[1]), "r"((a)[2]), "r"((a)[3]), "r"(b0), "r"(b1))

template <int OUT_HALF>
__global__ __launch_bounds__(256, 2)
void gemm_mma(const __half* __restrict__ Ah,
              const __half* __restrict__ Bh,
              const float* __restrict__ bias,
              void* __restrict__ Cout)
{
    extern __shared__ __align__(128) char smem[];
    const uint32_t sb = smem_u32(smem);
    const int tid = threadIdx.x;
    const int lane = tid & 31;
    const int wid = tid >> 5;
    const int warp_m = wid & 3;        // 4 warps along M (32 rows each)
    const int warp_n = wid >> 2;       // 2 warps along N (64 cols each)
    const int row0 = blockIdx.y * 128;
    const int col0 = blockIdx.x * 128;

    const __half* gsrc[2];
    gsrc[0] = Ah + (size_t)row0 * GK;
    gsrc[1] = Bh + (size_t)col0 * GK;

    float acc[2][8][4];
#pragma unroll
    for (int mt = 0; mt < 2; mt++)
#pragma unroll
        for (int nt = 0; nt < 8; nt++)
#pragma unroll
            for (int j = 0; j < 4; j++)
                acc[mt][nt][j] = 0.0f;

#define ISSUE_STAGE(CH)                                                       \
    do {                                                                      \
        const int _k0 = (CH) * CH_K;                                          \
        const uint32_t _sbase = sb + ((CH) % NSTAGE) * STG;                   \
        _Pragma("unroll")                                                     \
        for (int _t = 0; _t < 2; _t++) {                                      \
            _Pragma("unroll")                                                 \
            for (int _j = 0; _j < 4; _j++) {                                  \
                int _idx = tid + _j * 256;     /* 0..1023 */                  \
                int _r = _idx >> 3;            /* 0..127 */                   \
                int _c = _idx & 7;             /* 16B chunk in row */         \
                const __half* _g = gsrc[_t] + (size_t)_r * GK + _k0 + _c * 8; \
                uint32_t _s = _sbase + _t * TSZ + _r * ROWB + _c * 16;        \
                asm volatile("cp.async.cg.shared.global [%0], [%1], 16;"      \
                             :: "r"(_s), "l"(_g));                            \
            }                                                                 \
        }                                                                     \
        asm volatile("cp.async.commit_group;");                               \
    } while (0)

    ISSUE_STAGE(0);
    ISSUE_STAGE(1);

    for (int ch = 0; ch < NCHUNK; ch++) {
        asm volatile("cp.async.wait_group 1;");
        __syncthreads();

        if (ch + 2 < NCHUNK) {
            ISSUE_STAGE(ch + 2);
        } else {
            asm volatile("cp.async.commit_group;");
        }

        const uint32_t stBase = sb + (ch % NSTAGE) * STG;
#pragma unroll
        for (int ks = 0; ks < 4; ks++) {
            // --- load ALL fragments for this ks-step up front ---
            uint32_t a[2][4], b[4][4];
            {
                const uint32_t kb = (ks * 16 + (lane >> 4) * 8) * 2;
#pragma unroll
                for (int mt = 0; mt < 2; mt++) {
                    uint32_t ad = stBase
                                + (warp_m * 32 + mt * 16 + (lane & 15)) * ROWB + kb;
                    LDMX4(a[mt], ad);
                }
            }
            {
                const uint32_t brow = warp_n * 64 + ((lane >> 4) & 1) * 8 + (lane & 7);
                const uint32_t bcol = (ks * 16 + ((lane >> 3) & 1) * 8) * 2;
#pragma unroll
                for (int pr = 0; pr < 4; pr++) {
                    uint32_t bd = stBase + TSZ + (brow + pr * 16) * ROWB + bcol;
                    LDMX4(b[pr], bd);
                }
            }
            // --- 16 MMAs as one block ---
#pragma unroll
            for (int pr = 0; pr < 4; pr++) {
#pragma unroll
                for (int mt = 0; mt < 2; mt++) {
                    MMAF16(acc[mt][2 * pr],     a[mt], b[pr][0], b[pr][1]);
                    MMAF16(acc[mt][2 * pr + 1], a[mt], b[pr][2], b[pr][3]);
                }
            }
        }
    }
#undef ISSUE_STAGE

    // Epilogue
#pragma unroll
    for (int mt = 0; mt < 2; mt++) {
        const int r = row0 + warp_m * 32 + mt * 16 + (lane >> 2);
#pragma unroll
        for (int nt = 0; nt < 8; nt++) {
            const int cc = col0 + warp_n * 64 + nt * 8 + (lane & 3) * 2;
            const float b0 = bias[cc], b1 = bias[cc + 1];
            float v00 = acc[mt][nt][0] + b0, v01 = acc[mt][nt][1] + b1;
            float v10 = acc[mt][nt][2] + b0, v11 = acc[mt][nt][3] + b1;
            if (OUT_HALF) {
                __half* C = (__half*)Cout;
                __half2 h0 = __floats2half2_rn(v00, v01);
                __half2 h1 = __floats2half2_rn(v10, v11);
                *(__half2*)(C + (size_t)r * GN + cc) = h0;
                *(__half2*)(C + (size_t)(r + 8) * GN + cc) = h1;
            } else {
                float* C = (float*)Cout;
                float2 v0, v1;
                v0.x = v00; v0.y = v01;
                v1.x = v10; v1.y = v11;
                *(float2*)(C + (size_t)r * GN + cc) = v0;
                *(float2*)(C + (size_t)(r + 8) * GN + cc) = v1;
            }
        }
    }
}

// ---------------------------------------------------------------------------
// Per-head dynamic-kernel conv; fp16 input (xproj), fp16 output (concat).
// 64 tokens per block, fp32 compute in smem.
// ---------------------------------------------------------------------------
#define TOK_PER_BLK 64
#define TILE_ROWS (TOK_PER_BLK + 2 * PADMAX)   // 84
#define CONV_SMEM ((TILE_ROWS * DH + DH * RANK + RANK * KMAX + RANK * DH + KMAX * DH) * 4)

__global__ __launch_bounds__(256)
void dka_conv_kernel(const __half* __restrict__ xp,
                     const float* __restrict__ Wc,
                     const float* __restrict__ A,
                     const float* __restrict__ V,
                     const float* __restrict__ base,
                     const float* __restrict__ alphas,
                     __half* __restrict__ chd)
{
    extern __shared__ __align__(16) char cms[];
    float* xs     = (float*)cms;                    // [TILE_ROWS][DH]
    float* Wc_s   = xs + TILE_ROWS * DH;            // [DH*RANK]
    float* A_s    = Wc_s + DH * RANK;               // [RANK*KMAX]
    float* V_s    = A_s + RANK * KMAX;              // [RANK*DH]
    float* base_s = V_s + RANK * DH;                // [KMAX*DH]

    const int tid  = threadIdx.x;
    const int lane = tid & 31;
    const int warp = tid >> 5;

    const int chunk = blockIdx.x;
    const int h     = blockIdx.y;
    const int b     = blockIdx.z;
    const int start = chunk * TOK_PER_BLK;

    const int KH   = (h < 2) ? 3 : (h < 4) ? 7 : (h < 6) ? 11 : 21;
    const int padH = KH >> 1;

    const __half* xp_base = xp + ((size_t)b * NTOK) * DMODEL + h * DH;
    for (int idx = tid; idx < TILE_ROWS * (DH / 8); idx += 256) {
        int row = idx >> 4;
        int c8  = (idx & 15) * 8;
        int gn  = start - PADMAX + row;
        float* dst = xs + row * DH + c8;
        if (gn >= 0 && gn < NTOK) {
            uint4 raw = *(const uint4*)(xp_base + (size_t)gn * DMODEL + c8);
            const __half2* hp = (const __half2*)&raw;
#pragma unroll
            for (int j = 0; j < 4; j++) {
                float2 f = __half22float2(hp[j]);
                dst[2 * j]     = f.x;
                dst[2 * j + 1] = f.y;
            }
        } else {
#pragma unroll
            for (int j = 0; j < 8; j++) dst[j] = 0.0f;
        }
    }
    for (int idx = tid; idx < DH * RANK; idx += 256)
        Wc_s[idx] = Wc[(size_t)h * DH * RANK + idx];
    for (int idx = tid; idx < RANK * KMAX; idx += 256)
        A_s[idx] = A[(size_t)h * RANK * KMAX + idx];
    for (int idx = tid; idx < RANK * DH; idx += 256)
        V_s[idx] = V[(size_t)h * RANK * DH + idx];
    for (int idx = tid; idx < KMAX * DH; idx += 256)
        base_s[idx] = base[(size_t)h * KMAX * DH + idx];
    __syncthreads();

    const float alpha = 1.0f / (1.0f + __expf(-alphas[h]));
    const float oma   = 1.0f - alpha;

    for (int it = 0; it < TOK_PER_BLK / 8; it++) {
        const int lt     = warp + 8 * it;
        const int center = lt + PADMAX;

        float xv[4];
#pragma unroll
        for (int i = 0; i < 4; i++)
            xv[i] = xs[center * DH + lane + 32 * i];

        float c0 = 0.f, c1 = 0.f, c2 = 0.f, c3 = 0.f;
#pragma unroll
        for (int i = 0; i < 4; i++) {
            int d = lane + 32 * i;
            float x = xv[i];
            c0 = fmaf(x, Wc_s[d * RANK + 0], c0);
            c1 = fmaf(x, Wc_s[d * RANK + 1], c1);
            c2 = fmaf(x, Wc_s[d * RANK + 2], c2);
            c3 = fmaf(x, Wc_s[d * RANK + 3], c3);
        }
#pragma unroll
        for (int off = 16; off > 0; off >>= 1) {
            c0 += __shfl_xor_sync(0xffffffffu, c0, off);
            c1 += __shfl_xor_sync(0xffffffffu, c1, off);
            c2 += __shfl_xor_sync(0xffffffffu, c2, off);
            c3 += __shfl_xor_sync(0xffffffffu, c3, off);
        }

        float acc[4] = {0.f, 0.f, 0.f, 0.f};
        for (int k = 0; k < KH; k++) {
            const float ca0 = c0 * A_s[0 * KMAX + k];
            const float ca1 = c1 * A_s[1 * KMAX + k];
            const float ca2 = c2 * A_s[2 * KMAX + k];
            const float ca3 = c3 * A_s[3 * KMAX + k];
            const float* xr = xs + (center - padH + k) * DH;
#pragma unroll
            for (int i = 0; i < 4; i++) {
                int d = lane + 32 * i;
                float dyn = ca0 * V_s[0 * DH + d]
                          + ca1 * V_s[1 * DH + d]
                          + ca2 * V_s[2 * DH + d]
                          + ca3 * V_s[3 * DH + d];
                float kh = alpha * dyn + oma * base_s[k * DH + d];
                acc[i] = fmaf(kh, xr[d], acc[i]);
            }
        }

        const int n = start + lt;
        const size_t ob = ((size_t)b * NTOK + n) * DMODEL + h * DH;
#pragma unroll
        for (int i = 0; i < 4; i++)
            chd[ob + lane + 32 * i] = __float2half_rn(acc[i]);
    }
}

// ---------------------------------------------------------------------------
// Launch
// ---------------------------------------------------------------------------
extern "C" void kernel_launch(void* const* d_in, const int* in_sizes, int n_in,
                              void* d_out, int out_size)
{
    const float* x      = (const float*)d_in[0];
    const float* W_in   = (const float*)d_in[1];
    const float* b_in   = (const float*)d_in[2];
    const float* W_out  = (const float*)d_in[3];
    const float* b_out  = (const float*)d_in[4];
    const float* Wc     = (const float*)d_in[5];
    const float* A      = (const float*)d_in[6];
    const float* V      = (const float*)d_in[7];
    const float* base   = (const float*)d_in[8];
    const float* alphas = (const float*)d_in[9];
    float* out = (float*)d_out;

    __half *xp16, *xh, *ch, *wi, *wo;
    cudaGetSymbolAddress((void**)&xp16, g_xp16);
    cudaGetSymbolAddress((void**)&xh, g_xh);
    cudaGetSymbolAddress((void**)&ch, g_ch);
    cudaGetSymbolAddress((void**)&wi, g_wi);
    cudaGetSymbolAddress((void**)&wo, g_wo);

    cudaFuncSetAttribute(gemm_mma<0>, cudaFuncAttributeMaxDynamicSharedMemorySize, GSMEM);
    cudaFuncSetAttribute(gemm_mma<1>, cudaFuncAttributeMaxDynamicSharedMemorySize, GSMEM);
    cudaFuncSetAttribute(dka_conv_kernel, cudaFuncAttributeMaxDynamicSharedMemorySize, CONV_SMEM);

    // Fused fp16 converts (x, W_in, W_out) in one launch
    cvt_all<<<XB + 2 * WB, 256>>>((const float4*)x, (const float4*)W_in,
                                  (const float4*)W_out,
                                  (uint2*)xh, (uint2*)wi, (uint2*)wo);
    // GEMM1: xp16 = fp16(x @ W_in^T + b_in)
    {
        dim3 grid(GN / 128, GM / 128);   // (8, 64)
        gemm_mma<1><<<grid, 256, GSMEM>>>(xh, wi, b_in, xp16);
    }
    // Per-head dynamic conv -> concat (fp16)
    {
        dim3 grid(NTOK / TOK_PER_BLK, NHEADS, Bsz);
        dka_conv_kernel<<<grid, 256, CONV_SMEM>>>(xp16, Wc, A, V, base, alphas, ch);
    }
    // GEMM2: out = concat @ W_out^T + b_out   (fp32 out)
    {
        dim3 grid(GN / 128, GM / 128);
        gemm_mma<0><<<grid, 256, GSMEM>>>(ch, wo, b_out, out);
    }
}